// round 11
// baseline (speedup 1.0000x reference)
#include <cuda_runtime.h>
#include <cuda_bf16.h>
#include <stdint.h>
#include <math.h>

#define IN_DIM 64
#define HID    128
#define OUTD   128
#define ETILE  192          // edges per CTA-tile (12 warps x 16)
#define NTHR   384
#define MAXN   100000

// ------------------------- scratch (no-alloc rule) --------------------------
__device__ float g_src_proj[(size_t)MAXN * HID];
__device__ float g_dst_proj[(size_t)MAXN * HID];

// ------------------------- helpers ------------------------------------------
__device__ __forceinline__ uint32_t smem_u32(const void* p) {
    uint32_t a;
    asm("{ .reg .u64 t; cvta.to.shared.u64 t, %1; cvt.u32.u64 %0, t; }" : "=r"(a) : "l"(p));
    return a;
}
__device__ __forceinline__ void ldsm4(uint32_t* r, uint32_t addr) {
    asm volatile("ldmatrix.sync.aligned.m8n8.x4.shared.b16 {%0,%1,%2,%3}, [%4];"
                 : "=r"(r[0]), "=r"(r[1]), "=r"(r[2]), "=r"(r[3]) : "r"(addr));
}
__device__ __forceinline__ void mma16816(float* d, const uint32_t* a, const uint32_t* b) {
    asm volatile("mma.sync.aligned.m16n8k16.row.col.f32.bf16.bf16.f32 "
                 "{%0,%1,%2,%3}, {%4,%5,%6,%7}, {%8,%9}, {%0,%1,%2,%3};"
                 : "+f"(d[0]), "+f"(d[1]), "+f"(d[2]), "+f"(d[3])
                 : "r"(a[0]), "r"(a[1]), "r"(a[2]), "r"(a[3]), "r"(b[0]), "r"(b[1]));
}
__device__ __forceinline__ void mma_f16(float* d, const uint32_t* a, uint32_t b0, uint32_t b1) {
    asm volatile("mma.sync.aligned.m16n8k16.row.col.f32.f16.f16.f32 "
                 "{%0,%1,%2,%3}, {%4,%5,%6,%7}, {%8,%9}, {%0,%1,%2,%3};"
                 : "+f"(d[0]), "+f"(d[1]), "+f"(d[2]), "+f"(d[3])
                 : "r"(a[0]), "r"(a[1]), "r"(a[2]), "r"(a[3]), "r"(b0), "r"(b1));
}
// pack (x -> low half, y -> high half) as f16x2
__device__ __forceinline__ uint32_t h2pack(float x, float y) {
    uint32_t r;
    asm("cvt.rn.f16x2.f32 %0, %1, %2;" : "=r"(r) : "f"(y), "f"(x));
    return r;
}
__device__ __forceinline__ void split_pack(float x, float y, uint32_t& h, uint32_t& l) {
    __nv_bfloat16 xh = __float2bfloat16(x), yh = __float2bfloat16(y);
    __nv_bfloat16 xl = __float2bfloat16(x - __bfloat162float(xh));
    __nv_bfloat16 yl = __float2bfloat16(y - __bfloat162float(yh));
    h = (uint32_t)(*(uint16_t*)&xh) | ((uint32_t)(*(uint16_t*)&yh) << 16);
    l = (uint32_t)(*(uint16_t*)&xl) | ((uint32_t)(*(uint16_t*)&yl) << 16);
}
__device__ __forceinline__ float fsilu(float x) { return x / (1.0f + __expf(-x)); }

// ------------------------- smem layouts --------------------------------------
// edge kernel
#define OFF_F1 0          // 1024 uint4 = 16384 B : [j(16)][s2(2)][lane(32)]
#define OFF_F2 16384      // 2048 uint4 = 32768 B : [j(16)][s2(4)][lane(32)]
#define OFF_STG 49152     // 12 warps x 8192 B gather stage
#define OFF_BO 147456
#define OFF_GA 147968
#define OFF_BE 148480
#define SMEM_EDGE_BYTES 148992
// node kernel (bf16 3-term)
#define W1_STRIDE 72
#define OFF_NSH 0
#define OFF_NSL 18432
#define OFF_NDH 36864
#define OFF_NDL 55296
#define OFF_NB1 73728
#define SMEM_NODE_BYTES 74240

__device__ __forceinline__ void stage_w64(const float* __restrict__ W,
                                          __nv_bfloat16* sH, __nv_bfloat16* sL, int tid, int nthr) {
    for (int i = tid; i < HID * (IN_DIM / 2); i += nthr) {
        int n = i >> 5, p = i & 31;
        float2 f = ((const float2*)W)[n * 32 + p];
        __nv_bfloat16 xh = __float2bfloat16(f.x), yh = __float2bfloat16(f.y);
        sH[n * W1_STRIDE + 2 * p]     = xh;
        sH[n * W1_STRIDE + 2 * p + 1] = yh;
        sL[n * W1_STRIDE + 2 * p]     = __float2bfloat16(f.x - __bfloat162float(xh));
        sL[n * W1_STRIDE + 2 * p + 1] = __float2bfloat16(f.y - __bfloat162float(yh));
    }
}

// ---------------------------------------------------------------------------
// Kernel 1: node projections via HMMA bf16 3-term (near-exact) — unchanged
// ---------------------------------------------------------------------------
__global__ __launch_bounds__(256) void node_mma_kernel(
    const float* __restrict__ src_feat, const float* __restrict__ dst_feat,
    const float* __restrict__ W_src, const float* __restrict__ W_dst,
    const float* __restrict__ b1, int Nn, int ntilesN)
{
    extern __shared__ char smraw[];
    char* sm = smraw;
    const uint32_t base = smem_u32(smraw);
    const int tid = threadIdx.x;

    stage_w64(W_src, (__nv_bfloat16*)(sm + OFF_NSH), (__nv_bfloat16*)(sm + OFF_NSL), tid, 256);
    stage_w64(W_dst, (__nv_bfloat16*)(sm + OFF_NDH), (__nv_bfloat16*)(sm + OFF_NDL), tid, 256);
    if (tid < 128) ((float*)(sm + OFF_NB1))[tid] = b1[tid];
    __syncthreads();

    const int lane = tid & 31, warp = tid >> 5;
    const int qrow = lane >> 2, qcol = lane & 3;
    const int g = lane >> 3, r = lane & 7;
    const int lro = ((g & 2) ? 8 : 0) + r;
    const int lco = (g & 1) * 8;
    const uint32_t lmoff = (uint32_t)(lro * W1_STRIDE + lco) * 2;

    const int nitems = 2 * ntilesN;
    for (int item = blockIdx.x; item < nitems; item += gridDim.x) {
        const bool is_dst = (item >= ntilesN);
        const int tile = is_dst ? (item - ntilesN) : item;
        const float* X = is_dst ? dst_feat : src_feat;
        float* Out = is_dst ? g_dst_proj : g_src_proj;
        const uint32_t wh_base = base + (is_dst ? OFF_NDH : OFF_NSH) + lmoff;
        const uint32_t wl_base = base + (is_dst ? OFF_NDL : OFF_NSL) + lmoff;

        const int n0w = tile * 128 + warp * 16;
        const int nr0i = n0w + qrow, nr1i = nr0i + 8;
        const int gn0 = (nr0i < Nn) ? nr0i : (Nn - 1);
        const int gn1 = (nr1i < Nn) ? nr1i : (Nn - 1);
        const float* xr0 = X + (size_t)gn0 * IN_DIM + 2 * qcol;
        const float* xr1 = X + (size_t)gn1 * IN_DIM + 2 * qcol;

        uint32_t aH[4][4], aL[4][4];
        #pragma unroll
        for (int s = 0; s < 4; s++) {
            float2 f0 = *(const float2*)(xr0 + 16 * s);
            float2 f1 = *(const float2*)(xr1 + 16 * s);
            float2 f2 = *(const float2*)(xr0 + 16 * s + 8);
            float2 f3 = *(const float2*)(xr1 + 16 * s + 8);
            split_pack(f0.x, f0.y, aH[s][0], aL[s][0]);
            split_pack(f1.x, f1.y, aH[s][1], aL[s][1]);
            split_pack(f2.x, f2.y, aH[s][2], aL[s][2]);
            split_pack(f3.x, f3.y, aH[s][3], aL[s][3]);
        }

        float acc[16][4];
        #pragma unroll
        for (int j = 0; j < 16; j++) { acc[j][0]=0.f; acc[j][1]=0.f; acc[j][2]=0.f; acc[j][3]=0.f; }

        #pragma unroll
        for (int s = 0; s < 4; s++) {
            uint32_t bH[8][4], bL[8][4];
            #pragma unroll
            for (int jp = 0; jp < 8; jp++)
                ldsm4(bH[jp], wh_base + (uint32_t)(jp * 16 * W1_STRIDE + 16 * s) * 2);
            #pragma unroll
            for (int jp = 0; jp < 8; jp++) {
                mma16816(acc[2*jp],   aH[s], bH[jp]);
                mma16816(acc[2*jp+1], aH[s], bH[jp] + 2);
            }
            #pragma unroll
            for (int jp = 0; jp < 8; jp++)
                ldsm4(bL[jp], wl_base + (uint32_t)(jp * 16 * W1_STRIDE + 16 * s) * 2);
            #pragma unroll
            for (int jp = 0; jp < 8; jp++) {
                mma16816(acc[2*jp],   aL[s], bH[jp]);
                mma16816(acc[2*jp+1], aL[s], bH[jp] + 2);
            }
            #pragma unroll
            for (int jp = 0; jp < 8; jp++) {
                mma16816(acc[2*jp],   aH[s], bL[jp]);
                mma16816(acc[2*jp+1], aH[s], bL[jp] + 2);
            }
        }

        const float* sb1 = (const float*)(sm + OFF_NB1);
        const bool st0 = (nr0i < Nn), st1 = (nr1i < Nn);
        float* o0 = Out + (size_t)nr0i * HID + 2 * qcol;
        float* o1 = Out + (size_t)nr1i * HID + 2 * qcol;
        #pragma unroll
        for (int j = 0; j < 16; j++) {
            float2 bb = make_float2(0.f, 0.f);
            if (is_dst) bb = *(const float2*)(sb1 + 8 * j + 2 * qcol);
            if (st0) *(float2*)(o0 + 8 * j) = make_float2(acc[j][0] + bb.x, acc[j][1] + bb.y);
            if (st1) *(float2*)(o1 + 8 * j) = make_float2(acc[j][2] + bb.x, acc[j][3] + bb.y);
        }
    }
}

// ---------------------------------------------------------------------------
// Kernel 2: persistent FP16 edge pipeline, coalesced swizzled gather staging
// ---------------------------------------------------------------------------
__global__ __launch_bounds__(NTHR, 1) void edge_f16_kernel(
    const float* __restrict__ efeat,
    const int* __restrict__ src_idx, const int* __restrict__ dst_idx,
    const float* __restrict__ W_efeat, const float* __restrict__ W_out,
    const float* __restrict__ b_out, const float* __restrict__ gamma,
    const float* __restrict__ beta,
    float* __restrict__ out, int E, int ntiles)
{
    extern __shared__ char smraw[];
    char* sm = smraw;
    const int tid = threadIdx.x;

    // ---- stage W1 frags: [j(16)][s2(2)][lane(32)]
    {
        uint4* f1s = (uint4*)(sm + OFF_F1);
        for (int idx = tid; idx < 1024; idx += NTHR) {
            int j = idx >> 6, rem = idx & 63;
            int s2 = rem >> 5, l = rem & 31;
            int q = l & 3, rho = l >> 2;
            int L = ((rho >> 1) << 5) + 2 * j + (rho & 1);
            const float* wr = W_efeat + L * IN_DIM + q * 16 + s2 * 8;
            float4 wa = *(const float4*)wr;
            float4 wb = *(const float4*)(wr + 4);
            f1s[idx] = make_uint4(h2pack(wa.x, wa.y), h2pack(wa.z, wa.w),
                                  h2pack(wb.x, wb.y), h2pack(wb.z, wb.w));
        }
    }
    // ---- stage W2 frags: [j(16)][s2(4)][lane(32)]
    {
        uint4* f2s = (uint4*)(sm + OFF_F2);
        for (int idx = tid; idx < 2048; idx += NTHR) {
            int j = idx >> 7, rem = idx & 127;
            int s2 = rem >> 5, l = rem & 31;
            int q = l & 3, rho = l >> 2;
            int n = 8 * j + rho;
            const float* wr = W_out + n * HID + q * 32 + s2 * 8;
            float4 wa = *(const float4*)wr;
            float4 wb = *(const float4*)(wr + 4);
            f2s[idx] = make_uint4(h2pack(wa.x, wa.y), h2pack(wa.z, wa.w),
                                  h2pack(wb.x, wb.y), h2pack(wb.z, wb.w));
        }
    }
    if (tid < 128) {
        ((float*)(sm + OFF_BO))[tid] = b_out[tid];
        ((float*)(sm + OFF_GA))[tid] = gamma[tid];
        ((float*)(sm + OFF_BE))[tid] = beta[tid];
    }
    __syncthreads();

    const float* sBO = (const float*)(sm + OFF_BO);
    const float* sGA = (const float*)(sm + OFF_GA);
    const float* sBE = (const float*)(sm + OFF_BE);
    const uint4* f1 = (const uint4*)(sm + OFF_F1);
    const uint4* f2 = (const uint4*)(sm + OFF_F2);

    const int lane = tid & 31, warp = tid >> 5;
    const int qrow = lane >> 2, qcol = lane & 3;
    char* smst = sm + OFF_STG + warp * 8192;                // warp-private stage
    const int rho_l = ((lane & 7) << 2) | (lane >> 3);      // store swizzle of lane seg
    const int rd_s_base = qcol;                              // ((s<<2)|qcol) built in loop

    for (int tile = blockIdx.x; tile < ntiles; tile += gridDim.x) {
        const int e0w = tile * ETILE + warp * 16;
        const int er0i = e0w + qrow, er1i = er0i + 8;
        const int ge0 = (er0i < E) ? er0i : (E - 1);
        const int ge1 = (er1i < E) ? er1i : (E - 1);

        // lane-held gather indices: lanes 0-15 -> src_idx, 16-31 -> dst_idx
        int eL = e0w + (lane & 15); if (eL >= E) eL = E - 1;
        const int myidx = (lane < 16) ? src_idx[eL] : dst_idx[eL];

        // ---- A1 fragments (fp16) ----
        uint32_t a1f[4][4];
        {
            const float4* e0p = (const float4*)(efeat + (size_t)ge0 * IN_DIM + qcol * 16);
            const float4* e1p = (const float4*)(efeat + (size_t)ge1 * IN_DIM + qcol * 16);
            #pragma unroll
            for (int s = 0; s < 4; s++) {
                float4 v0 = e0p[s], v1 = e1p[s];
                a1f[s][0] = h2pack(v0.x, v0.y);
                a1f[s][1] = h2pack(v1.x, v1.y);
                a1f[s][2] = h2pack(v0.z, v0.w);
                a1f[s][3] = h2pack(v1.z, v1.w);
            }
        }

        // ---- GEMM1: 16x128x64 per warp, fp16 k16 ----
        float acc1[16][4];
        #pragma unroll
        for (int j = 0; j < 16; j++) { acc1[j][0]=0.f; acc1[j][1]=0.f; acc1[j][2]=0.f; acc1[j][3]=0.f; }
        #pragma unroll
        for (int s2 = 0; s2 < 2; s2++) {
            #pragma unroll
            for (int jg = 0; jg < 4; jg++) {
                const int n0 = 4 * jg;
                uint4 b0 = f1[((n0 + 0) * 2 + s2) * 32 + lane];
                uint4 b1 = f1[((n0 + 1) * 2 + s2) * 32 + lane];
                uint4 b2 = f1[((n0 + 2) * 2 + s2) * 32 + lane];
                uint4 b3 = f1[((n0 + 3) * 2 + s2) * 32 + lane];
                mma_f16(acc1[n0+0], a1f[2*s2],   b0.x, b0.y);
                mma_f16(acc1[n0+1], a1f[2*s2],   b1.x, b1.y);
                mma_f16(acc1[n0+2], a1f[2*s2],   b2.x, b2.y);
                mma_f16(acc1[n0+3], a1f[2*s2],   b3.x, b3.y);
                mma_f16(acc1[n0+0], a1f[2*s2+1], b0.z, b0.w);
                mma_f16(acc1[n0+1], a1f[2*s2+1], b1.z, b1.w);
                mma_f16(acc1[n0+2], a1f[2*s2+1], b2.z, b2.w);
                mma_f16(acc1[n0+3], a1f[2*s2+1], b3.z, b3.w);
            }
        }

        // ---- src pass: coalesced row loads -> swizzled stage -> acc1 += src ----
        #pragma unroll
        for (int i = 0; i < 16; i++) {
            int row = __shfl_sync(0xffffffffu, myidx, i);
            float4 v = *(const float4*)(g_src_proj + (size_t)row * HID + lane * 4);
            *(float4*)(smst + (size_t)((i * 32 + (rho_l ^ (i & 7))) * 16)) = v;
        }
        __syncwarp();
        #pragma unroll
        for (int s = 0; s < 8; s++) {
            int sw = (s << 2) | rd_s_base;
            float4 gs0 = *(const float4*)(smst + (size_t)(((qrow     ) * 32 + (sw ^ qrow)) * 16));
            float4 gs1 = *(const float4*)(smst + (size_t)(((qrow +  8) * 32 + (sw ^ qrow)) * 16));
            acc1[2*s][0]   += gs0.x; acc1[2*s][1]   += gs0.y;
            acc1[2*s+1][0] += gs0.z; acc1[2*s+1][1] += gs0.w;
            acc1[2*s][2]   += gs1.x; acc1[2*s][3]   += gs1.y;
            acc1[2*s+1][2] += gs1.z; acc1[2*s+1][3] += gs1.w;
        }
        __syncwarp();

        // ---- dst pass: coalesced -> stage -> SiLU + pack A2 frags ----
        #pragma unroll
        for (int i = 0; i < 16; i++) {
            int row = __shfl_sync(0xffffffffu, myidx, 16 + i);
            float4 v = *(const float4*)(g_dst_proj + (size_t)row * HID + lane * 4);
            *(float4*)(smst + (size_t)((i * 32 + (rho_l ^ (i & 7))) * 16)) = v;
        }
        __syncwarp();
        uint32_t a2f[8][4];
        #pragma unroll
        for (int s = 0; s < 8; s++) {
            int sw = (s << 2) | rd_s_base;
            float4 gd0 = *(const float4*)(smst + (size_t)(((qrow     ) * 32 + (sw ^ qrow)) * 16));
            float4 gd1 = *(const float4*)(smst + (size_t)(((qrow +  8) * 32 + (sw ^ qrow)) * 16));
            float u0 = fsilu(acc1[2*s][0]   + gd0.x);
            float u1 = fsilu(acc1[2*s][1]   + gd0.y);
            float u2 = fsilu(acc1[2*s+1][0] + gd0.z);
            float u3 = fsilu(acc1[2*s+1][1] + gd0.w);
            float w0 = fsilu(acc1[2*s][2]   + gd1.x);
            float w1 = fsilu(acc1[2*s][3]   + gd1.y);
            float w2 = fsilu(acc1[2*s+1][2] + gd1.z);
            float w3 = fsilu(acc1[2*s+1][3] + gd1.w);
            a2f[s][0] = h2pack(u0, u1);
            a2f[s][1] = h2pack(w0, w1);
            a2f[s][2] = h2pack(u2, u3);
            a2f[s][3] = h2pack(w2, w3);
        }
        __syncwarp();

        // ---- GEMM2: 16x128x128 per warp, fp16 k16 ----
        float acc2[16][4];
        #pragma unroll
        for (int j = 0; j < 16; j++) { acc2[j][0]=0.f; acc2[j][1]=0.f; acc2[j][2]=0.f; acc2[j][3]=0.f; }
        #pragma unroll
        for (int s2 = 0; s2 < 4; s2++) {
            #pragma unroll
            for (int jg = 0; jg < 4; jg++) {
                const int n0 = 4 * jg;
                uint4 b0 = f2[((n0 + 0) * 4 + s2) * 32 + lane];
                uint4 b1 = f2[((n0 + 1) * 4 + s2) * 32 + lane];
                uint4 b2 = f2[((n0 + 2) * 4 + s2) * 32 + lane];
                uint4 b3 = f2[((n0 + 3) * 4 + s2) * 32 + lane];
                mma_f16(acc2[n0+0], a2f[2*s2],   b0.x, b0.y);
                mma_f16(acc2[n0+1], a2f[2*s2],   b1.x, b1.y);
                mma_f16(acc2[n0+2], a2f[2*s2],   b2.x, b2.y);
                mma_f16(acc2[n0+3], a2f[2*s2],   b3.x, b3.y);
                mma_f16(acc2[n0+0], a2f[2*s2+1], b0.z, b0.w);
                mma_f16(acc2[n0+1], a2f[2*s2+1], b1.z, b1.w);
                mma_f16(acc2[n0+2], a2f[2*s2+1], b2.z, b2.w);
                mma_f16(acc2[n0+3], a2f[2*s2+1], b3.z, b3.w);
            }
        }

        // ---- bias + LayerNorm (quad shuffle) + store ----
        float s0 = 0.f, ss0 = 0.f, s1 = 0.f, ss1 = 0.f;
        #pragma unroll
        for (int j = 0; j < 16; j++) {
            float2 bo = *(const float2*)(sBO + 8 * j + 2 * qcol);
            acc2[j][0] += bo.x; acc2[j][1] += bo.y;
            acc2[j][2] += bo.x; acc2[j][3] += bo.y;
            s0  += acc2[j][0] + acc2[j][1];
            ss0 += acc2[j][0] * acc2[j][0] + acc2[j][1] * acc2[j][1];
            s1  += acc2[j][2] + acc2[j][3];
            ss1 += acc2[j][2] * acc2[j][2] + acc2[j][3] * acc2[j][3];
        }
        s0  += __shfl_xor_sync(0xffffffffu, s0, 1);  s0  += __shfl_xor_sync(0xffffffffu, s0, 2);
        ss0 += __shfl_xor_sync(0xffffffffu, ss0, 1); ss0 += __shfl_xor_sync(0xffffffffu, ss0, 2);
        s1  += __shfl_xor_sync(0xffffffffu, s1, 1);  s1  += __shfl_xor_sync(0xffffffffu, s1, 2);
        ss1 += __shfl_xor_sync(0xffffffffu, ss1, 1); ss1 += __shfl_xor_sync(0xffffffffu, ss1, 2);

        const float m0 = s0 * (1.0f / OUTD);
        const float v0 = ss0 * (1.0f / OUTD) - m0 * m0;
        const float i0 = rsqrtf(v0 + 1e-5f);
        const float m1 = s1 * (1.0f / OUTD);
        const float v1 = ss1 * (1.0f / OUTD) - m1 * m1;
        const float i1 = rsqrtf(v1 + 1e-5f);

        const bool st0 = (er0i < E), st1 = (er1i < E);
        float* o0 = out + (size_t)er0i * OUTD + 2 * qcol;
        float* o1 = out + (size_t)er1i * OUTD + 2 * qcol;
        #pragma unroll
        for (int j = 0; j < 16; j++) {
            float2 ga = *(const float2*)(sGA + 8 * j + 2 * qcol);
            float2 be = *(const float2*)(sBE + 8 * j + 2 * qcol);
            if (st0) {
                float2 w;
                w.x = (acc2[j][0] - m0) * i0 * ga.x + be.x;
                w.y = (acc2[j][1] - m0) * i0 * ga.y + be.y;
                *(float2*)(o0 + 8 * j) = w;
            }
            if (st1) {
                float2 w;
                w.x = (acc2[j][2] - m1) * i1 * ga.x + be.x;
                w.y = (acc2[j][3] - m1) * i1 * ga.y + be.y;
                *(float2*)(o1 + 8 * j) = w;
            }
        }
    }
}

// ---------------------------------------------------------------------------
extern "C" void kernel_launch(void* const* d_in, const int* in_sizes, int n_in,
                              void* d_out, int out_size)
{
    const float* efeat    = (const float*)d_in[0];
    const float* src_feat = (const float*)d_in[1];
    const float* dst_feat = (const float*)d_in[2];
    const int*   src_idx  = (const int*)d_in[3];
    const int*   dst_idx  = (const int*)d_in[4];
    const float* W_efeat  = (const float*)d_in[5];
    const float* W_src    = (const float*)d_in[6];
    const float* W_dst    = (const float*)d_in[7];
    const float* b1       = (const float*)d_in[8];
    const float* W_out    = (const float*)d_in[9];
    const float* b_out    = (const float*)d_in[10];
    const float* ln_gamma = (const float*)d_in[11];
    const float* ln_beta  = (const float*)d_in[12];
    float* out = (float*)d_out;

    const int E  = in_sizes[0] / IN_DIM;
    const int Nn = in_sizes[1] / IN_DIM;
    const int ntiles  = (E + ETILE - 1) / ETILE;
    const int ntilesN = (Nn + 127) / 128;

    cudaFuncSetAttribute(node_mma_kernel, cudaFuncAttributeMaxDynamicSharedMemorySize, SMEM_NODE_BYTES);
    cudaFuncSetAttribute(edge_f16_kernel, cudaFuncAttributeMaxDynamicSharedMemorySize, SMEM_EDGE_BYTES);

    int nsm = 148;
    cudaDeviceGetAttribute(&nsm, cudaDevAttrMultiProcessorCount, 0);

    int gridN = 2 * ntilesN < nsm ? 2 * ntilesN : nsm;
    node_mma_kernel<<<gridN, 256, SMEM_NODE_BYTES>>>(src_feat, dst_feat, W_src, W_dst, b1, Nn, ntilesN);

    int grid = (ntiles < nsm) ? ntiles : nsm;
    edge_f16_kernel<<<grid, NTHR, SMEM_EDGE_BYTES>>>(efeat, src_idx, dst_idx, W_efeat, W_out,
                                                     b_out, ln_gamma, ln_beta, out, E, ntiles);
}

// round 12
// speedup vs baseline: 1.0559x; 1.0559x over previous
#include <cuda_runtime.h>
#include <cuda_bf16.h>
#include <stdint.h>
#include <math.h>

#define IN_DIM 64
#define HID    128
#define OUTD   128
#define ETILE  160          // edges per CTA-tile (10 warps x 16)
#define NTHR   320
#define MAXN   100000

// ------------------------- scratch (no-alloc rule) --------------------------
__device__ float g_src_proj[(size_t)MAXN * HID];
__device__ float g_dst_proj[(size_t)MAXN * HID];

// ------------------------- helpers ------------------------------------------
__device__ __forceinline__ uint32_t smem_u32(const void* p) {
    uint32_t a;
    asm("{ .reg .u64 t; cvta.to.shared.u64 t, %1; cvt.u32.u64 %0, t; }" : "=r"(a) : "l"(p));
    return a;
}
__device__ __forceinline__ void ldsm4(uint32_t* r, uint32_t addr) {
    asm volatile("ldmatrix.sync.aligned.m8n8.x4.shared.b16 {%0,%1,%2,%3}, [%4];"
                 : "=r"(r[0]), "=r"(r[1]), "=r"(r[2]), "=r"(r[3]) : "r"(addr));
}
__device__ __forceinline__ void mma16816(float* d, const uint32_t* a, const uint32_t* b) {
    asm volatile("mma.sync.aligned.m16n8k16.row.col.f32.bf16.bf16.f32 "
                 "{%0,%1,%2,%3}, {%4,%5,%6,%7}, {%8,%9}, {%0,%1,%2,%3};"
                 : "+f"(d[0]), "+f"(d[1]), "+f"(d[2]), "+f"(d[3])
                 : "r"(a[0]), "r"(a[1]), "r"(a[2]), "r"(a[3]), "r"(b[0]), "r"(b[1]));
}
__device__ __forceinline__ void mma_f16(float* d, const uint32_t* a, uint32_t b0, uint32_t b1) {
    asm volatile("mma.sync.aligned.m16n8k16.row.col.f32.f16.f16.f32 "
                 "{%0,%1,%2,%3}, {%4,%5,%6,%7}, {%8,%9}, {%0,%1,%2,%3};"
                 : "+f"(d[0]), "+f"(d[1]), "+f"(d[2]), "+f"(d[3])
                 : "r"(a[0]), "r"(a[1]), "r"(a[2]), "r"(a[3]), "r"(b0), "r"(b1));
}
// pack (x -> low half, y -> high half) as f16x2
__device__ __forceinline__ uint32_t h2pack(float x, float y) {
    uint32_t r;
    asm("cvt.rn.f16x2.f32 %0, %1, %2;" : "=r"(r) : "f"(y), "f"(x));
    return r;
}
__device__ __forceinline__ void split_pack(float x, float y, uint32_t& h, uint32_t& l) {
    __nv_bfloat16 xh = __float2bfloat16(x), yh = __float2bfloat16(y);
    __nv_bfloat16 xl = __float2bfloat16(x - __bfloat162float(xh));
    __nv_bfloat16 yl = __float2bfloat16(y - __bfloat162float(yh));
    h = (uint32_t)(*(uint16_t*)&xh) | ((uint32_t)(*(uint16_t*)&yh) << 16);
    l = (uint32_t)(*(uint16_t*)&xl) | ((uint32_t)(*(uint16_t*)&yl) << 16);
}
__device__ __forceinline__ float fsilu(float x) { return x / (1.0f + __expf(-x)); }

// ------------------------- smem layouts --------------------------------------
// edge kernel
#define OFF_F1 0          // 1024 uint4 = 16384 B : [j(16)][s2(2)][lane(32)]
#define OFF_F2 16384      // 2048 uint4 = 32768 B : [j(16)][s2(4)][lane(32)]
#define OFF_STG 49152     // 10 warps x 16384 B gather stage (src 8K + dst 8K)
#define OFF_BO 212992
#define OFF_GA 213504
#define OFF_BE 214016
#define SMEM_EDGE_BYTES 214528
// node kernel (bf16 3-term)
#define W1_STRIDE 72
#define OFF_NSH 0
#define OFF_NSL 18432
#define OFF_NDH 36864
#define OFF_NDL 55296
#define OFF_NB1 73728
#define SMEM_NODE_BYTES 74240

__device__ __forceinline__ void stage_w64(const float* __restrict__ W,
                                          __nv_bfloat16* sH, __nv_bfloat16* sL, int tid, int nthr) {
    for (int i = tid; i < HID * (IN_DIM / 2); i += nthr) {
        int n = i >> 5, p = i & 31;
        float2 f = ((const float2*)W)[n * 32 + p];
        __nv_bfloat16 xh = __float2bfloat16(f.x), yh = __float2bfloat16(f.y);
        sH[n * W1_STRIDE + 2 * p]     = xh;
        sH[n * W1_STRIDE + 2 * p + 1] = yh;
        sL[n * W1_STRIDE + 2 * p]     = __float2bfloat16(f.x - __bfloat162float(xh));
        sL[n * W1_STRIDE + 2 * p + 1] = __float2bfloat16(f.y - __bfloat162float(yh));
    }
}

// ---------------------------------------------------------------------------
// Kernel 1: node projections via HMMA bf16 3-term (near-exact) — unchanged
// ---------------------------------------------------------------------------
__global__ __launch_bounds__(256) void node_mma_kernel(
    const float* __restrict__ src_feat, const float* __restrict__ dst_feat,
    const float* __restrict__ W_src, const float* __restrict__ W_dst,
    const float* __restrict__ b1, int Nn, int ntilesN)
{
    extern __shared__ char smraw[];
    char* sm = smraw;
    const uint32_t base = smem_u32(smraw);
    const int tid = threadIdx.x;

    stage_w64(W_src, (__nv_bfloat16*)(sm + OFF_NSH), (__nv_bfloat16*)(sm + OFF_NSL), tid, 256);
    stage_w64(W_dst, (__nv_bfloat16*)(sm + OFF_NDH), (__nv_bfloat16*)(sm + OFF_NDL), tid, 256);
    if (tid < 128) ((float*)(sm + OFF_NB1))[tid] = b1[tid];
    __syncthreads();

    const int lane = tid & 31, warp = tid >> 5;
    const int qrow = lane >> 2, qcol = lane & 3;
    const int g = lane >> 3, r = lane & 7;
    const int lro = ((g & 2) ? 8 : 0) + r;
    const int lco = (g & 1) * 8;
    const uint32_t lmoff = (uint32_t)(lro * W1_STRIDE + lco) * 2;

    const int nitems = 2 * ntilesN;
    for (int item = blockIdx.x; item < nitems; item += gridDim.x) {
        const bool is_dst = (item >= ntilesN);
        const int tile = is_dst ? (item - ntilesN) : item;
        const float* X = is_dst ? dst_feat : src_feat;
        float* Out = is_dst ? g_dst_proj : g_src_proj;
        const uint32_t wh_base = base + (is_dst ? OFF_NDH : OFF_NSH) + lmoff;
        const uint32_t wl_base = base + (is_dst ? OFF_NDL : OFF_NSL) + lmoff;

        const int n0w = tile * 128 + warp * 16;
        const int nr0i = n0w + qrow, nr1i = nr0i + 8;
        const int gn0 = (nr0i < Nn) ? nr0i : (Nn - 1);
        const int gn1 = (nr1i < Nn) ? nr1i : (Nn - 1);
        const float* xr0 = X + (size_t)gn0 * IN_DIM + 2 * qcol;
        const float* xr1 = X + (size_t)gn1 * IN_DIM + 2 * qcol;

        uint32_t aH[4][4], aL[4][4];
        #pragma unroll
        for (int s = 0; s < 4; s++) {
            float2 f0 = *(const float2*)(xr0 + 16 * s);
            float2 f1 = *(const float2*)(xr1 + 16 * s);
            float2 f2 = *(const float2*)(xr0 + 16 * s + 8);
            float2 f3 = *(const float2*)(xr1 + 16 * s + 8);
            split_pack(f0.x, f0.y, aH[s][0], aL[s][0]);
            split_pack(f1.x, f1.y, aH[s][1], aL[s][1]);
            split_pack(f2.x, f2.y, aH[s][2], aL[s][2]);
            split_pack(f3.x, f3.y, aH[s][3], aL[s][3]);
        }

        float acc[16][4];
        #pragma unroll
        for (int j = 0; j < 16; j++) { acc[j][0]=0.f; acc[j][1]=0.f; acc[j][2]=0.f; acc[j][3]=0.f; }

        #pragma unroll
        for (int s = 0; s < 4; s++) {
            uint32_t bH[8][4], bL[8][4];
            #pragma unroll
            for (int jp = 0; jp < 8; jp++)
                ldsm4(bH[jp], wh_base + (uint32_t)(jp * 16 * W1_STRIDE + 16 * s) * 2);
            #pragma unroll
            for (int jp = 0; jp < 8; jp++) {
                mma16816(acc[2*jp],   aH[s], bH[jp]);
                mma16816(acc[2*jp+1], aH[s], bH[jp] + 2);
            }
            #pragma unroll
            for (int jp = 0; jp < 8; jp++)
                ldsm4(bL[jp], wl_base + (uint32_t)(jp * 16 * W1_STRIDE + 16 * s) * 2);
            #pragma unroll
            for (int jp = 0; jp < 8; jp++) {
                mma16816(acc[2*jp],   aL[s], bH[jp]);
                mma16816(acc[2*jp+1], aL[s], bH[jp] + 2);
            }
            #pragma unroll
            for (int jp = 0; jp < 8; jp++) {
                mma16816(acc[2*jp],   aH[s], bL[jp]);
                mma16816(acc[2*jp+1], aH[s], bL[jp] + 2);
            }
        }

        const float* sb1 = (const float*)(sm + OFF_NB1);
        const bool st0 = (nr0i < Nn), st1 = (nr1i < Nn);
        float* o0 = Out + (size_t)nr0i * HID + 2 * qcol;
        float* o1 = Out + (size_t)nr1i * HID + 2 * qcol;
        #pragma unroll
        for (int j = 0; j < 16; j++) {
            float2 bb = make_float2(0.f, 0.f);
            if (is_dst) bb = *(const float2*)(sb1 + 8 * j + 2 * qcol);
            if (st0) *(float2*)(o0 + 8 * j) = make_float2(acc[j][0] + bb.x, acc[j][1] + bb.y);
            if (st1) *(float2*)(o1 + 8 * j) = make_float2(acc[j][2] + bb.x, acc[j][3] + bb.y);
        }
    }
}

// ---------------------------------------------------------------------------
// Kernel 2: persistent FP16 edge pipeline; coalesced gather staged into
// swizzled smem BEFORE GEMM1 (latency hidden behind MMAs), consumed after.
// ---------------------------------------------------------------------------
__global__ __launch_bounds__(NTHR, 1) void edge_f16_kernel(
    const float* __restrict__ efeat,
    const int* __restrict__ src_idx, const int* __restrict__ dst_idx,
    const float* __restrict__ W_efeat, const float* __restrict__ W_out,
    const float* __restrict__ b_out, const float* __restrict__ gamma,
    const float* __restrict__ beta,
    float* __restrict__ out, int E, int ntiles)
{
    extern __shared__ char smraw[];
    char* sm = smraw;
    const int tid = threadIdx.x;

    // ---- stage W1 frags: [j(16)][s2(2)][lane(32)]
    {
        uint4* f1s = (uint4*)(sm + OFF_F1);
        for (int idx = tid; idx < 1024; idx += NTHR) {
            int j = idx >> 6, rem = idx & 63;
            int s2 = rem >> 5, l = rem & 31;
            int q = l & 3, rho = l >> 2;
            int L = ((rho >> 1) << 5) + 2 * j + (rho & 1);
            const float* wr = W_efeat + L * IN_DIM + q * 16 + s2 * 8;
            float4 wa = *(const float4*)wr;
            float4 wb = *(const float4*)(wr + 4);
            f1s[idx] = make_uint4(h2pack(wa.x, wa.y), h2pack(wa.z, wa.w),
                                  h2pack(wb.x, wb.y), h2pack(wb.z, wb.w));
        }
    }
    // ---- stage W2 frags: [j(16)][s2(4)][lane(32)]
    {
        uint4* f2s = (uint4*)(sm + OFF_F2);
        for (int idx = tid; idx < 2048; idx += NTHR) {
            int j = idx >> 7, rem = idx & 127;
            int s2 = rem >> 5, l = rem & 31;
            int q = l & 3, rho = l >> 2;
            int n = 8 * j + rho;
            const float* wr = W_out + n * HID + q * 32 + s2 * 8;
            float4 wa = *(const float4*)wr;
            float4 wb = *(const float4*)(wr + 4);
            f2s[idx] = make_uint4(h2pack(wa.x, wa.y), h2pack(wa.z, wa.w),
                                  h2pack(wb.x, wb.y), h2pack(wb.z, wb.w));
        }
    }
    if (tid < 128) {
        ((float*)(sm + OFF_BO))[tid] = b_out[tid];
        ((float*)(sm + OFF_GA))[tid] = gamma[tid];
        ((float*)(sm + OFF_BE))[tid] = beta[tid];
    }
    __syncthreads();

    const float* sBO = (const float*)(sm + OFF_BO);
    const float* sGA = (const float*)(sm + OFF_GA);
    const float* sBE = (const float*)(sm + OFF_BE);
    const uint4* f1 = (const uint4*)(sm + OFF_F1);
    const uint4* f2 = (const uint4*)(sm + OFF_F2);

    const int lane = tid & 31, warp = tid >> 5;
    const int qrow = lane >> 2, qcol = lane & 3;
    char* smstS = sm + OFF_STG + warp * 16384;          // src stage (8 KB)
    char* smstD = smstS + 8192;                         // dst stage (8 KB)
    const int rho_l = ((lane & 7) << 2) | (lane >> 3);  // store swizzle of lane seg

    for (int tile = blockIdx.x; tile < ntiles; tile += gridDim.x) {
        const int e0w = tile * ETILE + warp * 16;
        const int er0i = e0w + qrow, er1i = er0i + 8;
        const int ge0 = (er0i < E) ? er0i : (E - 1);
        const int ge1 = (er1i < E) ? er1i : (E - 1);

        // lane-held gather indices: lanes 0-15 -> src_idx, 16-31 -> dst_idx
        int eL = e0w + (lane & 15); if (eL >= E) eL = E - 1;
        const int myidx = (lane < 16) ? src_idx[eL] : dst_idx[eL];

        // ---- stage BOTH gather batches now; consumed after GEMM1 ----
        #pragma unroll
        for (int i = 0; i < 16; i++) {
            int row = __shfl_sync(0xffffffffu, myidx, i);
            float4 v = *(const float4*)(g_src_proj + (size_t)row * HID + lane * 4);
            *(float4*)(smstS + (size_t)((i * 32 + (rho_l ^ (i & 7))) * 16)) = v;
        }
        #pragma unroll
        for (int i = 0; i < 16; i++) {
            int row = __shfl_sync(0xffffffffu, myidx, 16 + i);
            float4 v = *(const float4*)(g_dst_proj + (size_t)row * HID + lane * 4);
            *(float4*)(smstD + (size_t)((i * 32 + (rho_l ^ (i & 7))) * 16)) = v;
        }

        // ---- A1 fragments (fp16) ----
        uint32_t a1f[4][4];
        {
            const float4* e0p = (const float4*)(efeat + (size_t)ge0 * IN_DIM + qcol * 16);
            const float4* e1p = (const float4*)(efeat + (size_t)ge1 * IN_DIM + qcol * 16);
            #pragma unroll
            for (int s = 0; s < 4; s++) {
                float4 v0 = e0p[s], v1 = e1p[s];
                a1f[s][0] = h2pack(v0.x, v0.y);
                a1f[s][1] = h2pack(v1.x, v1.y);
                a1f[s][2] = h2pack(v0.z, v0.w);
                a1f[s][3] = h2pack(v1.z, v1.w);
            }
        }

        // ---- GEMM1: 16x128x64 per warp, fp16 k16 (hides gather latency) ----
        float acc1[16][4];
        #pragma unroll
        for (int j = 0; j < 16; j++) { acc1[j][0]=0.f; acc1[j][1]=0.f; acc1[j][2]=0.f; acc1[j][3]=0.f; }
        #pragma unroll
        for (int s2 = 0; s2 < 2; s2++) {
            #pragma unroll
            for (int jg = 0; jg < 4; jg++) {
                const int n0 = 4 * jg;
                uint4 b0 = f1[((n0 + 0) * 2 + s2) * 32 + lane];
                uint4 b1 = f1[((n0 + 1) * 2 + s2) * 32 + lane];
                uint4 b2 = f1[((n0 + 2) * 2 + s2) * 32 + lane];
                uint4 b3 = f1[((n0 + 3) * 2 + s2) * 32 + lane];
                mma_f16(acc1[n0+0], a1f[2*s2],   b0.x, b0.y);
                mma_f16(acc1[n0+1], a1f[2*s2],   b1.x, b1.y);
                mma_f16(acc1[n0+2], a1f[2*s2],   b2.x, b2.y);
                mma_f16(acc1[n0+3], a1f[2*s2],   b3.x, b3.y);
                mma_f16(acc1[n0+0], a1f[2*s2+1], b0.z, b0.w);
                mma_f16(acc1[n0+1], a1f[2*s2+1], b1.z, b1.w);
                mma_f16(acc1[n0+2], a1f[2*s2+1], b2.z, b2.w);
                mma_f16(acc1[n0+3], a1f[2*s2+1], b3.z, b3.w);
            }
        }
        __syncwarp();

        // ---- consume src stage: acc1 += src ----
        #pragma unroll
        for (int s = 0; s < 8; s++) {
            int sw = (s << 2) | qcol;
            float4 gs0 = *(const float4*)(smstS + (size_t)(((qrow     ) * 32 + (sw ^ qrow)) * 16));
            float4 gs1 = *(const float4*)(smstS + (size_t)(((qrow +  8) * 32 + (sw ^ qrow)) * 16));
            acc1[2*s][0]   += gs0.x; acc1[2*s][1]   += gs0.y;
            acc1[2*s+1][0] += gs0.z; acc1[2*s+1][1] += gs0.w;
            acc1[2*s][2]   += gs1.x; acc1[2*s][3]   += gs1.y;
            acc1[2*s+1][2] += gs1.z; acc1[2*s+1][3] += gs1.w;
        }

        // ---- consume dst stage: SiLU + pack A2 frags ----
        uint32_t a2f[8][4];
        #pragma unroll
        for (int s = 0; s < 8; s++) {
            int sw = (s << 2) | qcol;
            float4 gd0 = *(const float4*)(smstD + (size_t)(((qrow     ) * 32 + (sw ^ qrow)) * 16));
            float4 gd1 = *(const float4*)(smstD + (size_t)(((qrow +  8) * 32 + (sw ^ qrow)) * 16));
            float u0 = fsilu(acc1[2*s][0]   + gd0.x);
            float u1 = fsilu(acc1[2*s][1]   + gd0.y);
            float u2 = fsilu(acc1[2*s+1][0] + gd0.z);
            float u3 = fsilu(acc1[2*s+1][1] + gd0.w);
            float w0 = fsilu(acc1[2*s][2]   + gd1.x);
            float w1 = fsilu(acc1[2*s][3]   + gd1.y);
            float w2 = fsilu(acc1[2*s+1][2] + gd1.z);
            float w3 = fsilu(acc1[2*s+1][3] + gd1.w);
            a2f[s][0] = h2pack(u0, u1);
            a2f[s][1] = h2pack(w0, w1);
            a2f[s][2] = h2pack(u2, u3);
            a2f[s][3] = h2pack(w2, w3);
        }
        __syncwarp();

        // ---- GEMM2: 16x128x128 per warp, fp16 k16 ----
        float acc2[16][4];
        #pragma unroll
        for (int j = 0; j < 16; j++) { acc2[j][0]=0.f; acc2[j][1]=0.f; acc2[j][2]=0.f; acc2[j][3]=0.f; }
        #pragma unroll
        for (int s2 = 0; s2 < 4; s2++) {
            #pragma unroll
            for (int jg = 0; jg < 4; jg++) {
                const int n0 = 4 * jg;
                uint4 b0 = f2[((n0 + 0) * 4 + s2) * 32 + lane];
                uint4 b1 = f2[((n0 + 1) * 4 + s2) * 32 + lane];
                uint4 b2 = f2[((n0 + 2) * 4 + s2) * 32 + lane];
                uint4 b3 = f2[((n0 + 3) * 4 + s2) * 32 + lane];
                mma_f16(acc2[n0+0], a2f[2*s2],   b0.x, b0.y);
                mma_f16(acc2[n0+1], a2f[2*s2],   b1.x, b1.y);
                mma_f16(acc2[n0+2], a2f[2*s2],   b2.x, b2.y);
                mma_f16(acc2[n0+3], a2f[2*s2],   b3.x, b3.y);
                mma_f16(acc2[n0+0], a2f[2*s2+1], b0.z, b0.w);
                mma_f16(acc2[n0+1], a2f[2*s2+1], b1.z, b1.w);
                mma_f16(acc2[n0+2], a2f[2*s2+1], b2.z, b2.w);
                mma_f16(acc2[n0+3], a2f[2*s2+1], b3.z, b3.w);
            }
        }

        // ---- bias + LayerNorm (quad shuffle) + store ----
        float s0 = 0.f, ss0 = 0.f, s1 = 0.f, ss1 = 0.f;
        #pragma unroll
        for (int j = 0; j < 16; j++) {
            float2 bo = *(const float2*)(sBO + 8 * j + 2 * qcol);
            acc2[j][0] += bo.x; acc2[j][1] += bo.y;
            acc2[j][2] += bo.x; acc2[j][3] += bo.y;
            s0  += acc2[j][0] + acc2[j][1];
            ss0 += acc2[j][0] * acc2[j][0] + acc2[j][1] * acc2[j][1];
            s1  += acc2[j][2] + acc2[j][3];
            ss1 += acc2[j][2] * acc2[j][2] + acc2[j][3] * acc2[j][3];
        }
        s0  += __shfl_xor_sync(0xffffffffu, s0, 1);  s0  += __shfl_xor_sync(0xffffffffu, s0, 2);
        ss0 += __shfl_xor_sync(0xffffffffu, ss0, 1); ss0 += __shfl_xor_sync(0xffffffffu, ss0, 2);
        s1  += __shfl_xor_sync(0xffffffffu, s1, 1);  s1  += __shfl_xor_sync(0xffffffffu, s1, 2);
        ss1 += __shfl_xor_sync(0xffffffffu, ss1, 1); ss1 += __shfl_xor_sync(0xffffffffu, ss1, 2);

        const float m0 = s0 * (1.0f / OUTD);
        const float v0 = ss0 * (1.0f / OUTD) - m0 * m0;
        const float i0 = rsqrtf(v0 + 1e-5f);
        const float m1 = s1 * (1.0f / OUTD);
        const float v1 = ss1 * (1.0f / OUTD) - m1 * m1;
        const float i1 = rsqrtf(v1 + 1e-5f);

        const bool st0 = (er0i < E), st1 = (er1i < E);
        float* o0 = out + (size_t)er0i * OUTD + 2 * qcol;
        float* o1 = out + (size_t)er1i * OUTD + 2 * qcol;
        #pragma unroll
        for (int j = 0; j < 16; j++) {
            float2 ga = *(const float2*)(sGA + 8 * j + 2 * qcol);
            float2 be = *(const float2*)(sBE + 8 * j + 2 * qcol);
            if (st0) {
                float2 w;
                w.x = (acc2[j][0] - m0) * i0 * ga.x + be.x;
                w.y = (acc2[j][1] - m0) * i0 * ga.y + be.y;
                *(float2*)(o0 + 8 * j) = w;
            }
            if (st1) {
                float2 w;
                w.x = (acc2[j][2] - m1) * i1 * ga.x + be.x;
                w.y = (acc2[j][3] - m1) * i1 * ga.y + be.y;
                *(float2*)(o1 + 8 * j) = w;
            }
        }
        __syncwarp();   // stage buffers reused next tile
    }
}

// ---------------------------------------------------------------------------
extern "C" void kernel_launch(void* const* d_in, const int* in_sizes, int n_in,
                              void* d_out, int out_size)
{
    const float* efeat    = (const float*)d_in[0];
    const float* src_feat = (const float*)d_in[1];
    const float* dst_feat = (const float*)d_in[2];
    const int*   src_idx  = (const int*)d_in[3];
    const int*   dst_idx  = (const int*)d_in[4];
    const float* W_efeat  = (const float*)d_in[5];
    const float* W_src    = (const float*)d_in[6];
    const float* W_dst    = (const float*)d_in[7];
    const float* b1       = (const float*)d_in[8];
    const float* W_out    = (const float*)d_in[9];
    const float* b_out    = (const float*)d_in[10];
    const float* ln_gamma = (const float*)d_in[11];
    const float* ln_beta  = (const float*)d_in[12];
    float* out = (float*)d_out;

    const int E  = in_sizes[0] / IN_DIM;
    const int Nn = in_sizes[1] / IN_DIM;
    const int ntiles  = (E + ETILE - 1) / ETILE;
    const int ntilesN = (Nn + 127) / 128;

    cudaFuncSetAttribute(node_mma_kernel, cudaFuncAttributeMaxDynamicSharedMemorySize, SMEM_NODE_BYTES);
    cudaFuncSetAttribute(edge_f16_kernel, cudaFuncAttributeMaxDynamicSharedMemorySize, SMEM_EDGE_BYTES);

    int nsm = 148;
    cudaDeviceGetAttribute(&nsm, cudaDevAttrMultiProcessorCount, 0);

    int gridN = 2 * ntilesN < nsm ? 2 * ntilesN : nsm;
    node_mma_kernel<<<gridN, 256, SMEM_NODE_BYTES>>>(src_feat, dst_feat, W_src, W_dst, b1, Nn, ntilesN);

    int grid = (ntiles < nsm) ? ntiles : nsm;
    edge_f16_kernel<<<grid, NTHR, SMEM_EDGE_BYTES>>>(efeat, src_idx, dst_idx, W_efeat, W_out,
                                                     b_out, ln_gamma, ln_beta, out, E, ntiles);
}

// round 13
// speedup vs baseline: 1.6251x; 1.5390x over previous
#include <cuda_runtime.h>
#include <cuda_bf16.h>
#include <cuda_fp16.h>
#include <stdint.h>
#include <math.h>

#define IN_DIM 64
#define HID    128
#define OUTD   128
#define ETILE  192          // edges per CTA-tile (12 warps x 16)
#define NTHR   384
#define MAXN   100000

// ------------------------- scratch (no-alloc rule) --------------------------
// node projections stored in fp16 (halves gather footprint)
__device__ __half g_src_proj[(size_t)MAXN * HID];
__device__ __half g_dst_proj[(size_t)MAXN * HID];

// ------------------------- helpers ------------------------------------------
__device__ __forceinline__ uint32_t smem_u32(const void* p) {
    uint32_t a;
    asm("{ .reg .u64 t; cvta.to.shared.u64 t, %1; cvt.u32.u64 %0, t; }" : "=r"(a) : "l"(p));
    return a;
}
__device__ __forceinline__ void ldsm4(uint32_t* r, uint32_t addr) {
    asm volatile("ldmatrix.sync.aligned.m8n8.x4.shared.b16 {%0,%1,%2,%3}, [%4];"
                 : "=r"(r[0]), "=r"(r[1]), "=r"(r[2]), "=r"(r[3]) : "r"(addr));
}
__device__ __forceinline__ void mma16816(float* d, const uint32_t* a, const uint32_t* b) {
    asm volatile("mma.sync.aligned.m16n8k16.row.col.f32.bf16.bf16.f32 "
                 "{%0,%1,%2,%3}, {%4,%5,%6,%7}, {%8,%9}, {%0,%1,%2,%3};"
                 : "+f"(d[0]), "+f"(d[1]), "+f"(d[2]), "+f"(d[3])
                 : "r"(a[0]), "r"(a[1]), "r"(a[2]), "r"(a[3]), "r"(b[0]), "r"(b[1]));
}
__device__ __forceinline__ void mma_f16(float* d, const uint32_t* a, uint32_t b0, uint32_t b1) {
    asm volatile("mma.sync.aligned.m16n8k16.row.col.f32.f16.f16.f32 "
                 "{%0,%1,%2,%3}, {%4,%5,%6,%7}, {%8,%9}, {%0,%1,%2,%3};"
                 : "+f"(d[0]), "+f"(d[1]), "+f"(d[2]), "+f"(d[3])
                 : "r"(a[0]), "r"(a[1]), "r"(a[2]), "r"(a[3]), "r"(b0), "r"(b1));
}
// pack (x -> low half, y -> high half) as f16x2
__device__ __forceinline__ uint32_t h2pack(float x, float y) {
    uint32_t r;
    asm("cvt.rn.f16x2.f32 %0, %1, %2;" : "=r"(r) : "f"(y), "f"(x));
    return r;
}
__device__ __forceinline__ float2 h2unpack(uint32_t u) {
    __half2 h = *reinterpret_cast<__half2*>(&u);
    return __half22float2(h);
}
__device__ __forceinline__ void split_pack(float x, float y, uint32_t& h, uint32_t& l) {
    __nv_bfloat16 xh = __float2bfloat16(x), yh = __float2bfloat16(y);
    __nv_bfloat16 xl = __float2bfloat16(x - __bfloat162float(xh));
    __nv_bfloat16 yl = __float2bfloat16(y - __bfloat162float(yh));
    h = (uint32_t)(*(uint16_t*)&xh) | ((uint32_t)(*(uint16_t*)&yh) << 16);
    l = (uint32_t)(*(uint16_t*)&xl) | ((uint32_t)(*(uint16_t*)&yl) << 16);
}
__device__ __forceinline__ float fsilu(float x) { return x / (1.0f + __expf(-x)); }

// ------------------------- smem layouts --------------------------------------
// edge kernel: W frags in fp16 frag-stream layout
#define OFF_F1 0          // 1024 uint4 = 16384 B : [j(16)][s2(2)][lane(32)]
#define OFF_F2 16384      // 2048 uint4 = 32768 B : [j(16)][s2(4)][lane(32)]
#define OFF_BO 49152
#define OFF_GA 49664
#define OFF_BE 50176
#define SMEM_EDGE_BYTES 50688
// node kernel (bf16 3-term)
#define W1_STRIDE 72
#define OFF_NSH 0
#define OFF_NSL 18432
#define OFF_NDH 36864
#define OFF_NDL 55296
#define OFF_NB1 73728
#define SMEM_NODE_BYTES 74240

__device__ __forceinline__ void stage_w64(const float* __restrict__ W,
                                          __nv_bfloat16* sH, __nv_bfloat16* sL, int tid, int nthr) {
    for (int i = tid; i < HID * (IN_DIM / 2); i += nthr) {
        int n = i >> 5, p = i & 31;
        float2 f = ((const float2*)W)[n * 32 + p];
        __nv_bfloat16 xh = __float2bfloat16(f.x), yh = __float2bfloat16(f.y);
        sH[n * W1_STRIDE + 2 * p]     = xh;
        sH[n * W1_STRIDE + 2 * p + 1] = yh;
        sL[n * W1_STRIDE + 2 * p]     = __float2bfloat16(f.x - __bfloat162float(xh));
        sL[n * W1_STRIDE + 2 * p + 1] = __float2bfloat16(f.y - __bfloat162float(yh));
    }
}

// ---------------------------------------------------------------------------
// Kernel 1: node projections via HMMA bf16 3-term (near-exact), fp16 output
// ---------------------------------------------------------------------------
__global__ __launch_bounds__(256) void node_mma_kernel(
    const float* __restrict__ src_feat, const float* __restrict__ dst_feat,
    const float* __restrict__ W_src, const float* __restrict__ W_dst,
    const float* __restrict__ b1, int Nn, int ntilesN)
{
    extern __shared__ char smraw[];
    char* sm = smraw;
    const uint32_t base = smem_u32(smraw);
    const int tid = threadIdx.x;

    stage_w64(W_src, (__nv_bfloat16*)(sm + OFF_NSH), (__nv_bfloat16*)(sm + OFF_NSL), tid, 256);
    stage_w64(W_dst, (__nv_bfloat16*)(sm + OFF_NDH), (__nv_bfloat16*)(sm + OFF_NDL), tid, 256);
    if (tid < 128) ((float*)(sm + OFF_NB1))[tid] = b1[tid];
    __syncthreads();

    const int lane = tid & 31, warp = tid >> 5;
    const int qrow = lane >> 2, qcol = lane & 3;
    const int g = lane >> 3, r = lane & 7;
    const int lro = ((g & 2) ? 8 : 0) + r;
    const int lco = (g & 1) * 8;
    const uint32_t lmoff = (uint32_t)(lro * W1_STRIDE + lco) * 2;

    const int nitems = 2 * ntilesN;
    for (int item = blockIdx.x; item < nitems; item += gridDim.x) {
        const bool is_dst = (item >= ntilesN);
        const int tile = is_dst ? (item - ntilesN) : item;
        const float* X = is_dst ? dst_feat : src_feat;
        __half* Out = is_dst ? g_dst_proj : g_src_proj;
        const uint32_t wh_base = base + (is_dst ? OFF_NDH : OFF_NSH) + lmoff;
        const uint32_t wl_base = base + (is_dst ? OFF_NDL : OFF_NSL) + lmoff;

        const int n0w = tile * 128 + warp * 16;
        const int nr0i = n0w + qrow, nr1i = nr0i + 8;
        const int gn0 = (nr0i < Nn) ? nr0i : (Nn - 1);
        const int gn1 = (nr1i < Nn) ? nr1i : (Nn - 1);
        const float* xr0 = X + (size_t)gn0 * IN_DIM + 2 * qcol;
        const float* xr1 = X + (size_t)gn1 * IN_DIM + 2 * qcol;

        uint32_t aH[4][4], aL[4][4];
        #pragma unroll
        for (int s = 0; s < 4; s++) {
            float2 f0 = *(const float2*)(xr0 + 16 * s);
            float2 f1 = *(const float2*)(xr1 + 16 * s);
            float2 f2 = *(const float2*)(xr0 + 16 * s + 8);
            float2 f3 = *(const float2*)(xr1 + 16 * s + 8);
            split_pack(f0.x, f0.y, aH[s][0], aL[s][0]);
            split_pack(f1.x, f1.y, aH[s][1], aL[s][1]);
            split_pack(f2.x, f2.y, aH[s][2], aL[s][2]);
            split_pack(f3.x, f3.y, aH[s][3], aL[s][3]);
        }

        float acc[16][4];
        #pragma unroll
        for (int j = 0; j < 16; j++) { acc[j][0]=0.f; acc[j][1]=0.f; acc[j][2]=0.f; acc[j][3]=0.f; }

        #pragma unroll
        for (int s = 0; s < 4; s++) {
            uint32_t bH[8][4], bL[8][4];
            #pragma unroll
            for (int jp = 0; jp < 8; jp++)
                ldsm4(bH[jp], wh_base + (uint32_t)(jp * 16 * W1_STRIDE + 16 * s) * 2);
            #pragma unroll
            for (int jp = 0; jp < 8; jp++) {
                mma16816(acc[2*jp],   aH[s], bH[jp]);
                mma16816(acc[2*jp+1], aH[s], bH[jp] + 2);
            }
            #pragma unroll
            for (int jp = 0; jp < 8; jp++)
                ldsm4(bL[jp], wl_base + (uint32_t)(jp * 16 * W1_STRIDE + 16 * s) * 2);
            #pragma unroll
            for (int jp = 0; jp < 8; jp++) {
                mma16816(acc[2*jp],   aL[s], bH[jp]);
                mma16816(acc[2*jp+1], aL[s], bH[jp] + 2);
            }
            #pragma unroll
            for (int jp = 0; jp < 8; jp++) {
                mma16816(acc[2*jp],   aH[s], bL[jp]);
                mma16816(acc[2*jp+1], aH[s], bL[jp] + 2);
            }
        }

        const float* sb1 = (const float*)(sm + OFF_NB1);
        const bool st0 = (nr0i < Nn), st1 = (nr1i < Nn);
        __half* o0 = Out + (size_t)nr0i * HID + 2 * qcol;
        __half* o1 = Out + (size_t)nr1i * HID + 2 * qcol;
        #pragma unroll
        for (int j = 0; j < 16; j++) {
            float2 bb = make_float2(0.f, 0.f);
            if (is_dst) bb = *(const float2*)(sb1 + 8 * j + 2 * qcol);
            if (st0) {
                uint32_t p = h2pack(acc[j][0] + bb.x, acc[j][1] + bb.y);
                *(uint32_t*)(o0 + 8 * j) = p;
            }
            if (st1) {
                uint32_t p = h2pack(acc[j][2] + bb.x, acc[j][3] + bb.y);
                *(uint32_t*)(o1 + 8 * j) = p;
            }
        }
    }
}

// ---------------------------------------------------------------------------
// Kernel 2: persistent FP16 edge pipeline (R10 structure), fp16 gathers
// ---------------------------------------------------------------------------
__global__ __launch_bounds__(NTHR, 1) void edge_f16_kernel(
    const float* __restrict__ efeat,
    const int* __restrict__ src_idx, const int* __restrict__ dst_idx,
    const float* __restrict__ W_efeat, const float* __restrict__ W_out,
    const float* __restrict__ b_out, const float* __restrict__ gamma,
    const float* __restrict__ beta,
    float* __restrict__ out, int E, int ntiles)
{
    extern __shared__ char smraw[];
    char* sm = smraw;
    const int tid = threadIdx.x;

    // ---- stage W1 frags: [j(16)][s2(2)][lane(32)]
    {
        uint4* f1s = (uint4*)(sm + OFF_F1);
        for (int idx = tid; idx < 1024; idx += NTHR) {
            int j = idx >> 6, rem = idx & 63;
            int s2 = rem >> 5, l = rem & 31;
            int q = l & 3, rho = l >> 2;
            int L = ((rho >> 1) << 5) + 2 * j + (rho & 1);
            const float* wr = W_efeat + L * IN_DIM + q * 16 + s2 * 8;
            float4 wa = *(const float4*)wr;
            float4 wb = *(const float4*)(wr + 4);
            f1s[idx] = make_uint4(h2pack(wa.x, wa.y), h2pack(wa.z, wa.w),
                                  h2pack(wb.x, wb.y), h2pack(wb.z, wb.w));
        }
    }
    // ---- stage W2 frags: [j(16)][s2(4)][lane(32)]
    {
        uint4* f2s = (uint4*)(sm + OFF_F2);
        for (int idx = tid; idx < 2048; idx += NTHR) {
            int j = idx >> 7, rem = idx & 127;
            int s2 = rem >> 5, l = rem & 31;
            int q = l & 3, rho = l >> 2;
            int n = 8 * j + rho;
            const float* wr = W_out + n * HID + q * 32 + s2 * 8;
            float4 wa = *(const float4*)wr;
            float4 wb = *(const float4*)(wr + 4);
            f2s[idx] = make_uint4(h2pack(wa.x, wa.y), h2pack(wa.z, wa.w),
                                  h2pack(wb.x, wb.y), h2pack(wb.z, wb.w));
        }
    }
    if (tid < 128) {
        ((float*)(sm + OFF_BO))[tid] = b_out[tid];
        ((float*)(sm + OFF_GA))[tid] = gamma[tid];
        ((float*)(sm + OFF_BE))[tid] = beta[tid];
    }
    __syncthreads();

    const float* sBO = (const float*)(sm + OFF_BO);
    const float* sGA = (const float*)(sm + OFF_GA);
    const float* sBE = (const float*)(sm + OFF_BE);
    const uint4* f1 = (const uint4*)(sm + OFF_F1);
    const uint4* f2 = (const uint4*)(sm + OFF_F2);

    const int lane = tid & 31, warp = tid >> 5;
    const int qrow = lane >> 2, qcol = lane & 3;

    for (int tile = blockIdx.x; tile < ntiles; tile += gridDim.x) {
        const int e0w = tile * ETILE + warp * 16;
        const int er0i = e0w + qrow, er1i = er0i + 8;
        const int ge0 = (er0i < E) ? er0i : (E - 1);
        const int ge1 = (er1i < E) ? er1i : (E - 1);

        // gather pointers: each thread's span = 32 contiguous halfs = 64 B
        const int si0 = src_idx[ge0], di0 = dst_idx[ge0];
        const int si1 = src_idx[ge1], di1 = dst_idx[ge1];
        const uint4* ps0 = (const uint4*)(g_src_proj + (size_t)si0 * HID + qcol * 32);
        const uint4* pd0 = (const uint4*)(g_dst_proj + (size_t)di0 * HID + qcol * 32);
        const uint4* ps1 = (const uint4*)(g_src_proj + (size_t)si1 * HID + qcol * 32);
        const uint4* pd1 = (const uint4*)(g_dst_proj + (size_t)di1 * HID + qcol * 32);
        asm volatile("prefetch.global.L2 [%0];" :: "l"(ps0));
        asm volatile("prefetch.global.L2 [%0];" :: "l"(pd0));
        asm volatile("prefetch.global.L2 [%0];" :: "l"(ps1));
        asm volatile("prefetch.global.L2 [%0];" :: "l"(pd1));

        // ---- A1 fragments (fp16) ----
        uint32_t a1f[4][4];
        {
            const float4* e0p = (const float4*)(efeat + (size_t)ge0 * IN_DIM + qcol * 16);
            const float4* e1p = (const float4*)(efeat + (size_t)ge1 * IN_DIM + qcol * 16);
            #pragma unroll
            for (int s = 0; s < 4; s++) {
                float4 v0 = e0p[s], v1 = e1p[s];
                a1f[s][0] = h2pack(v0.x, v0.y);
                a1f[s][1] = h2pack(v1.x, v1.y);
                a1f[s][2] = h2pack(v0.z, v0.w);
                a1f[s][3] = h2pack(v1.z, v1.w);
            }
        }

        // ---- GEMM1: 16x128x64 per warp, fp16 k16 ----
        float acc1[16][4];
        #pragma unroll
        for (int j = 0; j < 16; j++) { acc1[j][0]=0.f; acc1[j][1]=0.f; acc1[j][2]=0.f; acc1[j][3]=0.f; }
        #pragma unroll
        for (int s2 = 0; s2 < 2; s2++) {
            #pragma unroll
            for (int jg = 0; jg < 4; jg++) {
                const int n0 = 4 * jg;
                uint4 b0 = f1[((n0 + 0) * 2 + s2) * 32 + lane];
                uint4 b1 = f1[((n0 + 1) * 2 + s2) * 32 + lane];
                uint4 b2 = f1[((n0 + 2) * 2 + s2) * 32 + lane];
                uint4 b3 = f1[((n0 + 3) * 2 + s2) * 32 + lane];
                mma_f16(acc1[n0+0], a1f[2*s2],   b0.x, b0.y);
                mma_f16(acc1[n0+1], a1f[2*s2],   b1.x, b1.y);
                mma_f16(acc1[n0+2], a1f[2*s2],   b2.x, b2.y);
                mma_f16(acc1[n0+3], a1f[2*s2],   b3.x, b3.y);
                mma_f16(acc1[n0+0], a1f[2*s2+1], b0.z, b0.w);
                mma_f16(acc1[n0+1], a1f[2*s2+1], b1.z, b1.w);
                mma_f16(acc1[n0+2], a1f[2*s2+1], b2.z, b2.w);
                mma_f16(acc1[n0+3], a1f[2*s2+1], b3.z, b3.w);
            }
        }

        // ---- gather (fp16) + SiLU + pack GEMM2 A-frags ----
        // uint4 t holds halfs for cols qcol*32 + 8t .. 8t+7 (slices s=2t, 2t+1)
        uint32_t a2f[8][4];
        #pragma unroll
        for (int t = 0; t < 4; t++) {
            uint4 s0v = ps0[t], d0v = pd0[t];
            uint4 s1v = ps1[t], d1v = pd1[t];
            {   // s = 2t : .x (cols 4s,4s+1), .y (cols 4s+2,4s+3)
                const int s = 2 * t;
                float2 gs0a = h2unpack(s0v.x), gs0b = h2unpack(s0v.y);
                float2 gd0a = h2unpack(d0v.x), gd0b = h2unpack(d0v.y);
                float2 gs1a = h2unpack(s1v.x), gs1b = h2unpack(s1v.y);
                float2 gd1a = h2unpack(d1v.x), gd1b = h2unpack(d1v.y);
                float u0 = fsilu(acc1[2*s][0]   + gs0a.x + gd0a.x);
                float u1 = fsilu(acc1[2*s][1]   + gs0a.y + gd0a.y);
                float u2 = fsilu(acc1[2*s+1][0] + gs0b.x + gd0b.x);
                float u3 = fsilu(acc1[2*s+1][1] + gs0b.y + gd0b.y);
                float w0 = fsilu(acc1[2*s][2]   + gs1a.x + gd1a.x);
                float w1 = fsilu(acc1[2*s][3]   + gs1a.y + gd1a.y);
                float w2 = fsilu(acc1[2*s+1][2] + gs1b.x + gd1b.x);
                float w3 = fsilu(acc1[2*s+1][3] + gs1b.y + gd1b.y);
                a2f[s][0] = h2pack(u0, u1);
                a2f[s][1] = h2pack(w0, w1);
                a2f[s][2] = h2pack(u2, u3);
                a2f[s][3] = h2pack(w2, w3);
            }
            {   // s = 2t+1 : .z, .w
                const int s = 2 * t + 1;
                float2 gs0a = h2unpack(s0v.z), gs0b = h2unpack(s0v.w);
                float2 gd0a = h2unpack(d0v.z), gd0b = h2unpack(d0v.w);
                float2 gs1a = h2unpack(s1v.z), gs1b = h2unpack(s1v.w);
                float2 gd1a = h2unpack(d1v.z), gd1b = h2unpack(d1v.w);
                float u0 = fsilu(acc1[2*s][0]   + gs0a.x + gd0a.x);
                float u1 = fsilu(acc1[2*s][1]   + gs0a.y + gd0a.y);
                float u2 = fsilu(acc1[2*s+1][0] + gs0b.x + gd0b.x);
                float u3 = fsilu(acc1[2*s+1][1] + gs0b.y + gd0b.y);
                float w0 = fsilu(acc1[2*s][2]   + gs1a.x + gd1a.x);
                float w1 = fsilu(acc1[2*s][3]   + gs1a.y + gd1a.y);
                float w2 = fsilu(acc1[2*s+1][2] + gs1b.x + gd1b.x);
                float w3 = fsilu(acc1[2*s+1][3] + gs1b.y + gd1b.y);
                a2f[s][0] = h2pack(u0, u1);
                a2f[s][1] = h2pack(w0, w1);
                a2f[s][2] = h2pack(u2, u3);
                a2f[s][3] = h2pack(w2, w3);
            }
        }

        // ---- GEMM2: 16x128x128 per warp, fp16 k16 ----
        float acc2[16][4];
        #pragma unroll
        for (int j = 0; j < 16; j++) { acc2[j][0]=0.f; acc2[j][1]=0.f; acc2[j][2]=0.f; acc2[j][3]=0.f; }
        #pragma unroll
        for (int s2 = 0; s2 < 4; s2++) {
            #pragma unroll
            for (int jg = 0; jg < 4; jg++) {
                const int n0 = 4 * jg;
                uint4 b0 = f2[((n0 + 0) * 4 + s2) * 32 + lane];
                uint4 b1 = f2[((n0 + 1) * 4 + s2) * 32 + lane];
                uint4 b2 = f2[((n0 + 2) * 4 + s2) * 32 + lane];
                uint4 b3 = f2[((n0 + 3) * 4 + s2) * 32 + lane];
                mma_f16(acc2[n0+0], a2f[2*s2],   b0.x, b0.y);
                mma_f16(acc2[n0+1], a2f[2*s2],   b1.x, b1.y);
                mma_f16(acc2[n0+2], a2f[2*s2],   b2.x, b2.y);
                mma_f16(acc2[n0+3], a2f[2*s2],   b3.x, b3.y);
                mma_f16(acc2[n0+0], a2f[2*s2+1], b0.z, b0.w);
                mma_f16(acc2[n0+1], a2f[2*s2+1], b1.z, b1.w);
                mma_f16(acc2[n0+2], a2f[2*s2+1], b2.z, b2.w);
                mma_f16(acc2[n0+3], a2f[2*s2+1], b3.z, b3.w);
            }
        }

        // ---- bias + LayerNorm (quad shuffle) + store ----
        float s0 = 0.f, ss0 = 0.f, s1 = 0.f, ss1 = 0.f;
        #pragma unroll
        for (int j = 0; j < 16; j++) {
            float2 bo = *(const float2*)(sBO + 8 * j + 2 * qcol);
            acc2[j][0] += bo.x; acc2[j][1] += bo.y;
            acc2[j][2] += bo.x; acc2[j][3] += bo.y;
            s0  += acc2[j][0] + acc2[j][1];
            ss0 += acc2[j][0] * acc2[j][0] + acc2[j][1] * acc2[j][1];
            s1  += acc2[j][2] + acc2[j][3];
            ss1 += acc2[j][2] * acc2[j][2] + acc2[j][3] * acc2[j][3];
        }
        s0  += __shfl_xor_sync(0xffffffffu, s0, 1);  s0  += __shfl_xor_sync(0xffffffffu, s0, 2);
        ss0 += __shfl_xor_sync(0xffffffffu, ss0, 1); ss0 += __shfl_xor_sync(0xffffffffu, ss0, 2);
        s1  += __shfl_xor_sync(0xffffffffu, s1, 1);  s1  += __shfl_xor_sync(0xffffffffu, s1, 2);
        ss1 += __shfl_xor_sync(0xffffffffu, ss1, 1); ss1 += __shfl_xor_sync(0xffffffffu, ss1, 2);

        const float m0 = s0 * (1.0f / OUTD);
        const float v0 = ss0 * (1.0f / OUTD) - m0 * m0;
        const float i0 = rsqrtf(v0 + 1e-5f);
        const float m1 = s1 * (1.0f / OUTD);
        const float v1 = ss1 * (1.0f / OUTD) - m1 * m1;
        const float i1 = rsqrtf(v1 + 1e-5f);

        const bool st0 = (er0i < E), st1 = (er1i < E);
        float* o0 = out + (size_t)er0i * OUTD + 2 * qcol;
        float* o1 = out + (size_t)er1i * OUTD + 2 * qcol;
        #pragma unroll
        for (int j = 0; j < 16; j++) {
            float2 ga = *(const float2*)(sGA + 8 * j + 2 * qcol);
            float2 be = *(const float2*)(sBE + 8 * j + 2 * qcol);
            if (st0) {
                float2 w;
                w.x = (acc2[j][0] - m0) * i0 * ga.x + be.x;
                w.y = (acc2[j][1] - m0) * i0 * ga.y + be.y;
                *(float2*)(o0 + 8 * j) = w;
            }
            if (st1) {
                float2 w;
                w.x = (acc2[j][2] - m1) * i1 * ga.x + be.x;
                w.y = (acc2[j][3] - m1) * i1 * ga.y + be.y;
                *(float2*)(o1 + 8 * j) = w;
            }
        }
    }
}

// ---------------------------------------------------------------------------
extern "C" void kernel_launch(void* const* d_in, const int* in_sizes, int n_in,
                              void* d_out, int out_size)
{
    const float* efeat    = (const float*)d_in[0];
    const float* src_feat = (const float*)d_in[1];
    const float* dst_feat = (const float*)d_in[2];
    const int*   src_idx  = (const int*)d_in[3];
    const int*   dst_idx  = (const int*)d_in[4];
    const float* W_efeat  = (const float*)d_in[5];
    const float* W_src    = (const float*)d_in[6];
    const float* W_dst    = (const float*)d_in[7];
    const float* b1       = (const float*)d_in[8];
    const float* W_out    = (const float*)d_in[9];
    const float* b_out    = (const float*)d_in[10];
    const float* ln_gamma = (const float*)d_in[11];
    const float* ln_beta  = (const float*)d_in[12];
    float* out = (float*)d_out;

    const int E  = in_sizes[0] / IN_DIM;
    const int Nn = in_sizes[1] / IN_DIM;
    const int ntiles  = (E + ETILE - 1) / ETILE;
    const int ntilesN = (Nn + 127) / 128;

    cudaFuncSetAttribute(node_mma_kernel, cudaFuncAttributeMaxDynamicSharedMemorySize, SMEM_NODE_BYTES);
    cudaFuncSetAttribute(edge_f16_kernel, cudaFuncAttributeMaxDynamicSharedMemorySize, SMEM_EDGE_BYTES);

    int nsm = 148;
    cudaDeviceGetAttribute(&nsm, cudaDevAttrMultiProcessorCount, 0);

    int gridN = 2 * ntilesN < nsm ? 2 * ntilesN : nsm;
    node_mma_kernel<<<gridN, 256, SMEM_NODE_BYTES>>>(src_feat, dst_feat, W_src, W_dst, b1, Nn, ntilesN);

    int grid = (ntiles < nsm) ? ntiles : nsm;
    edge_f16_kernel<<<grid, NTHR, SMEM_EDGE_BYTES>>>(efeat, src_idx, dst_idx, W_efeat, W_out,
                                                     b_out, ln_gamma, ln_beta, out, E, ntiles);
}

// round 14
// speedup vs baseline: 1.7436x; 1.0729x over previous
#include <cuda_runtime.h>
#include <cuda_bf16.h>
#include <cuda_fp16.h>
#include <stdint.h>
#include <math.h>

#define IN_DIM 64
#define HID    128
#define OUTD   128
#define ETILE  192          // edges per CTA-tile (12 warps x 16)
#define NTHR   384
#define NROWS_N 192         // node rows per item (12 warps x 16)
#define MAXN   100000

// ------------------------- scratch (no-alloc rule) --------------------------
__device__ __half g_src_proj[(size_t)MAXN * HID];
__device__ __half g_dst_proj[(size_t)MAXN * HID];

// ------------------------- helpers ------------------------------------------
__device__ __forceinline__ uint32_t smem_u32(const void* p) {
    uint32_t a;
    asm("{ .reg .u64 t; cvta.to.shared.u64 t, %1; cvt.u32.u64 %0, t; }" : "=r"(a) : "l"(p));
    return a;
}
__device__ __forceinline__ void ldsm4(uint32_t* r, uint32_t addr) {
    asm volatile("ldmatrix.sync.aligned.m8n8.x4.shared.b16 {%0,%1,%2,%3}, [%4];"
                 : "=r"(r[0]), "=r"(r[1]), "=r"(r[2]), "=r"(r[3]) : "r"(addr));
}
__device__ __forceinline__ void mma_f16(float* d, const uint32_t* a, uint32_t b0, uint32_t b1) {
    asm volatile("mma.sync.aligned.m16n8k16.row.col.f32.f16.f16.f32 "
                 "{%0,%1,%2,%3}, {%4,%5,%6,%7}, {%8,%9}, {%0,%1,%2,%3};"
                 : "+f"(d[0]), "+f"(d[1]), "+f"(d[2]), "+f"(d[3])
                 : "r"(a[0]), "r"(a[1]), "r"(a[2]), "r"(a[3]), "r"(b0), "r"(b1));
}
__device__ __forceinline__ uint32_t h2pack(float x, float y) {
    uint32_t r;
    asm("cvt.rn.f16x2.f32 %0, %1, %2;" : "=r"(r) : "f"(y), "f"(x));
    return r;
}
__device__ __forceinline__ float2 h2unpack(uint32_t u) {
    __half2 h = *reinterpret_cast<__half2*>(&u);
    return __half22float2(h);
}
__device__ __forceinline__ float fsilu(float x) { return x / (1.0f + __expf(-x)); }

// ------------------------- smem layouts --------------------------------------
// edge kernel
#define OFF_F1 0          // 1024 uint4 = 16384 B : [j(16)][s2(2)][lane(32)]
#define OFF_F2 16384      // 2048 uint4 = 32768 B : [j(16)][s2(4)][lane(32)]
#define OFF_BO 49152
#define OFF_GA 49664
#define OFF_BE 50176
#define SMEM_EDGE_BYTES 50688
// node kernel (fp16 single-pass)
#define W1_STRIDE 72
#define OFF_NSH 0           // W_src fp16 [128][72] = 18432 B
#define OFF_NDH 18432       // W_dst fp16
#define OFF_NB1 36864
#define SMEM_NODE_BYTES 37376

// ---------------------------------------------------------------------------
// Kernel 1: node projections via fp16 HMMA single-pass, fp16 output
// ---------------------------------------------------------------------------
__global__ __launch_bounds__(NTHR) void node_mma_kernel(
    const float* __restrict__ src_feat, const float* __restrict__ dst_feat,
    const float* __restrict__ W_src, const float* __restrict__ W_dst,
    const float* __restrict__ b1, int Nn, int ntilesN)
{
    extern __shared__ char smraw[];
    char* sm = smraw;
    const uint32_t base = smem_u32(smraw);
    const int tid = threadIdx.x;

    // stage fp16 weights [n(128)][72 halfs], pad 8
    {
        __half* sS = (__half*)(sm + OFF_NSH);
        __half* sD = (__half*)(sm + OFF_NDH);
        for (int i = tid; i < HID * (IN_DIM / 2); i += NTHR) {
            int n = i >> 5, p = i & 31;
            float2 fs = ((const float2*)W_src)[n * 32 + p];
            float2 fd = ((const float2*)W_dst)[n * 32 + p];
            *(uint32_t*)(sS + n * W1_STRIDE + 2 * p) = h2pack(fs.x, fs.y);
            *(uint32_t*)(sD + n * W1_STRIDE + 2 * p) = h2pack(fd.x, fd.y);
        }
    }
    if (tid < 128) ((float*)(sm + OFF_NB1))[tid] = b1[tid];
    __syncthreads();

    const int lane = tid & 31, warp = tid >> 5;
    const int qrow = lane >> 2, qcol = lane & 3;
    const int g = lane >> 3, r = lane & 7;
    const int lro = ((g & 2) ? 8 : 0) + r;
    const int lco = (g & 1) * 8;
    const uint32_t lmoff = (uint32_t)(lro * W1_STRIDE + lco) * 2;

    const int nitems = 2 * ntilesN;
    for (int item = blockIdx.x; item < nitems; item += gridDim.x) {
        const bool is_dst = (item >= ntilesN);
        const int tile = is_dst ? (item - ntilesN) : item;
        const float* X = is_dst ? dst_feat : src_feat;
        __half* Out = is_dst ? g_dst_proj : g_src_proj;
        const uint32_t wbase = base + (is_dst ? OFF_NDH : OFF_NSH) + lmoff;

        const int n0w = tile * NROWS_N + warp * 16;
        const int nr0i = n0w + qrow, nr1i = nr0i + 8;
        const int gn0 = (nr0i < Nn) ? nr0i : (Nn - 1);
        const int gn1 = (nr1i < Nn) ? nr1i : (Nn - 1);
        const float* xr0 = X + (size_t)gn0 * IN_DIM + 2 * qcol;
        const float* xr1 = X + (size_t)gn1 * IN_DIM + 2 * qcol;

        uint32_t a[4][4];
        #pragma unroll
        for (int s = 0; s < 4; s++) {
            float2 f0 = *(const float2*)(xr0 + 16 * s);
            float2 f1 = *(const float2*)(xr1 + 16 * s);
            float2 f2 = *(const float2*)(xr0 + 16 * s + 8);
            float2 f3 = *(const float2*)(xr1 + 16 * s + 8);
            a[s][0] = h2pack(f0.x, f0.y);
            a[s][1] = h2pack(f1.x, f1.y);
            a[s][2] = h2pack(f2.x, f2.y);
            a[s][3] = h2pack(f3.x, f3.y);
        }

        float acc[16][4];
        #pragma unroll
        for (int j = 0; j < 16; j++) { acc[j][0]=0.f; acc[j][1]=0.f; acc[j][2]=0.f; acc[j][3]=0.f; }

        #pragma unroll
        for (int s = 0; s < 4; s++) {
            uint32_t bF[8][4];
            #pragma unroll
            for (int jp = 0; jp < 8; jp++)
                ldsm4(bF[jp], wbase + (uint32_t)(jp * 16 * W1_STRIDE + 16 * s) * 2);
            #pragma unroll
            for (int jp = 0; jp < 8; jp++) {
                mma_f16(acc[2*jp],   a[s], bF[jp][0], bF[jp][1]);
                mma_f16(acc[2*jp+1], a[s], bF[jp][2], bF[jp][3]);
            }
        }

        const float* sb1 = (const float*)(sm + OFF_NB1);
        const bool st0 = (nr0i < Nn), st1 = (nr1i < Nn);
        __half* o0 = Out + (size_t)nr0i * HID + 2 * qcol;
        __half* o1 = Out + (size_t)nr1i * HID + 2 * qcol;
        #pragma unroll
        for (int j = 0; j < 16; j++) {
            float2 bb = make_float2(0.f, 0.f);
            if (is_dst) bb = *(const float2*)(sb1 + 8 * j + 2 * qcol);
            if (st0) *(uint32_t*)(o0 + 8 * j) = h2pack(acc[j][0] + bb.x, acc[j][1] + bb.y);
            if (st1) *(uint32_t*)(o1 + 8 * j) = h2pack(acc[j][2] + bb.x, acc[j][3] + bb.y);
        }
    }
}

// ---------------------------------------------------------------------------
// Kernel 2: persistent FP16 edge pipeline; fp16 gathers; next-tile index
// software pipelining + L2 prefetch of next-tile gather/efeat rows.
// ---------------------------------------------------------------------------
__global__ __launch_bounds__(NTHR, 1) void edge_f16_kernel(
    const float* __restrict__ efeat,
    const int* __restrict__ src_idx, const int* __restrict__ dst_idx,
    const float* __restrict__ W_efeat, const float* __restrict__ W_out,
    const float* __restrict__ b_out, const float* __restrict__ gamma,
    const float* __restrict__ beta,
    float* __restrict__ out, int E, int ntiles)
{
    extern __shared__ char smraw[];
    char* sm = smraw;
    const int tid = threadIdx.x;

    // ---- stage W1 frags: [j(16)][s2(2)][lane(32)]
    {
        uint4* f1s = (uint4*)(sm + OFF_F1);
        for (int idx = tid; idx < 1024; idx += NTHR) {
            int j = idx >> 6, rem = idx & 63;
            int s2 = rem >> 5, l = rem & 31;
            int q = l & 3, rho = l >> 2;
            int L = ((rho >> 1) << 5) + 2 * j + (rho & 1);
            const float* wr = W_efeat + L * IN_DIM + q * 16 + s2 * 8;
            float4 wa = *(const float4*)wr;
            float4 wb = *(const float4*)(wr + 4);
            f1s[idx] = make_uint4(h2pack(wa.x, wa.y), h2pack(wa.z, wa.w),
                                  h2pack(wb.x, wb.y), h2pack(wb.z, wb.w));
        }
    }
    // ---- stage W2 frags: [j(16)][s2(4)][lane(32)]
    {
        uint4* f2s = (uint4*)(sm + OFF_F2);
        for (int idx = tid; idx < 2048; idx += NTHR) {
            int j = idx >> 7, rem = idx & 127;
            int s2 = rem >> 5, l = rem & 31;
            int q = l & 3, rho = l >> 2;
            int n = 8 * j + rho;
            const float* wr = W_out + n * HID + q * 32 + s2 * 8;
            float4 wa = *(const float4*)wr;
            float4 wb = *(const float4*)(wr + 4);
            f2s[idx] = make_uint4(h2pack(wa.x, wa.y), h2pack(wa.z, wa.w),
                                  h2pack(wb.x, wb.y), h2pack(wb.z, wb.w));
        }
    }
    if (tid < 128) {
        ((float*)(sm + OFF_BO))[tid] = b_out[tid];
        ((float*)(sm + OFF_GA))[tid] = gamma[tid];
        ((float*)(sm + OFF_BE))[tid] = beta[tid];
    }
    __syncthreads();

    const float* sBO = (const float*)(sm + OFF_BO);
    const float* sGA = (const float*)(sm + OFF_GA);
    const float* sBE = (const float*)(sm + OFF_BE);
    const uint4* f1 = (const uint4*)(sm + OFF_F1);
    const uint4* f2 = (const uint4*)(sm + OFF_F2);

    const int lane = tid & 31, warp = tid >> 5;
    const int qrow = lane >> 2, qcol = lane & 3;

    // preload first tile's indices
    int tile = blockIdx.x;
    int si0 = 0, di0 = 0, si1 = 0, di1 = 0;
    if (tile < ntiles) {
        const int e0w = tile * ETILE + warp * 16;
        int g0 = e0w + qrow;     if (g0 >= E) g0 = E - 1;
        int g1 = e0w + qrow + 8; if (g1 >= E) g1 = E - 1;
        si0 = src_idx[g0]; di0 = dst_idx[g0];
        si1 = src_idx[g1]; di1 = dst_idx[g1];
    }

    for (; tile < ntiles; ) {
        const int e0w = tile * ETILE + warp * 16;
        const int er0i = e0w + qrow, er1i = er0i + 8;
        const int ge0 = (er0i < E) ? er0i : (E - 1);
        const int ge1 = (er1i < E) ? er1i : (E - 1);

        const uint4* ps0 = (const uint4*)(g_src_proj + (size_t)si0 * HID + qcol * 32);
        const uint4* pd0 = (const uint4*)(g_dst_proj + (size_t)di0 * HID + qcol * 32);
        const uint4* ps1 = (const uint4*)(g_src_proj + (size_t)si1 * HID + qcol * 32);
        const uint4* pd1 = (const uint4*)(g_dst_proj + (size_t)di1 * HID + qcol * 32);

        // ---- A1 fragments (fp16) ----
        uint32_t a1f[4][4];
        {
            const float4* e0p = (const float4*)(efeat + (size_t)ge0 * IN_DIM + qcol * 16);
            const float4* e1p = (const float4*)(efeat + (size_t)ge1 * IN_DIM + qcol * 16);
            #pragma unroll
            for (int s = 0; s < 4; s++) {
                float4 v0 = e0p[s], v1 = e1p[s];
                a1f[s][0] = h2pack(v0.x, v0.y);
                a1f[s][1] = h2pack(v1.x, v1.y);
                a1f[s][2] = h2pack(v0.z, v0.w);
                a1f[s][3] = h2pack(v1.z, v1.w);
            }
        }

        // ---- GEMM1 ----
        float acc1[16][4];
        #pragma unroll
        for (int j = 0; j < 16; j++) { acc1[j][0]=0.f; acc1[j][1]=0.f; acc1[j][2]=0.f; acc1[j][3]=0.f; }
        #pragma unroll
        for (int s2 = 0; s2 < 2; s2++) {
            #pragma unroll
            for (int jg = 0; jg < 4; jg++) {
                const int n0 = 4 * jg;
                uint4 b0 = f1[((n0 + 0) * 2 + s2) * 32 + lane];
                uint4 b1 = f1[((n0 + 1) * 2 + s2) * 32 + lane];
                uint4 b2 = f1[((n0 + 2) * 2 + s2) * 32 + lane];
                uint4 b3 = f1[((n0 + 3) * 2 + s2) * 32 + lane];
                mma_f16(acc1[n0+0], a1f[2*s2],   b0.x, b0.y);
                mma_f16(acc1[n0+1], a1f[2*s2],   b1.x, b1.y);
                mma_f16(acc1[n0+2], a1f[2*s2],   b2.x, b2.y);
                mma_f16(acc1[n0+3], a1f[2*s2],   b3.x, b3.y);
                mma_f16(acc1[n0+0], a1f[2*s2+1], b0.z, b0.w);
                mma_f16(acc1[n0+1], a1f[2*s2+1], b1.z, b1.w);
                mma_f16(acc1[n0+2], a1f[2*s2+1], b2.z, b2.w);
                mma_f16(acc1[n0+3], a1f[2*s2+1], b3.z, b3.w);
            }
        }

        // ---- load NEXT tile's indices (latency hidden behind rest of tile) ----
        const int ntile = tile + gridDim.x;
        const bool hasnext = (ntile < ntiles);
        int nsi0 = 0, ndi0 = 0, nsi1 = 0, ndi1 = 0, nge0 = 0, nge1 = 0;
        if (hasnext) {
            const int ne0w = ntile * ETILE + warp * 16;
            nge0 = ne0w + qrow;     if (nge0 >= E) nge0 = E - 1;
            nge1 = ne0w + qrow + 8; if (nge1 >= E) nge1 = E - 1;
            nsi0 = src_idx[nge0]; ndi0 = dst_idx[nge0];
            nsi1 = src_idx[nge1]; ndi1 = dst_idx[nge1];
        }

        // ---- gather (fp16) + SiLU + pack GEMM2 A-frags ----
        uint32_t a2f[8][4];
        #pragma unroll
        for (int t = 0; t < 4; t++) {
            uint4 s0v = ps0[t], d0v = pd0[t];
            uint4 s1v = ps1[t], d1v = pd1[t];
            {
                const int s = 2 * t;
                float2 gs0a = h2unpack(s0v.x), gs0b = h2unpack(s0v.y);
                float2 gd0a = h2unpack(d0v.x), gd0b = h2unpack(d0v.y);
                float2 gs1a = h2unpack(s1v.x), gs1b = h2unpack(s1v.y);
                float2 gd1a = h2unpack(d1v.x), gd1b = h2unpack(d1v.y);
                float u0 = fsilu(acc1[2*s][0]   + gs0a.x + gd0a.x);
                float u1 = fsilu(acc1[2*s][1]   + gs0a.y + gd0a.y);
                float u2 = fsilu(acc1[2*s+1][0] + gs0b.x + gd0b.x);
                float u3 = fsilu(acc1[2*s+1][1] + gs0b.y + gd0b.y);
                float w0 = fsilu(acc1[2*s][2]   + gs1a.x + gd1a.x);
                float w1 = fsilu(acc1[2*s][3]   + gs1a.y + gd1a.y);
                float w2 = fsilu(acc1[2*s+1][2] + gs1b.x + gd1b.x);
                float w3 = fsilu(acc1[2*s+1][3] + gs1b.y + gd1b.y);
                a2f[s][0] = h2pack(u0, u1);
                a2f[s][1] = h2pack(w0, w1);
                a2f[s][2] = h2pack(u2, u3);
                a2f[s][3] = h2pack(w2, w3);
            }
            {
                const int s = 2 * t + 1;
                float2 gs0a = h2unpack(s0v.z), gs0b = h2unpack(s0v.w);
                float2 gd0a = h2unpack(d0v.z), gd0b = h2unpack(d0v.w);
                float2 gs1a = h2unpack(s1v.z), gs1b = h2unpack(s1v.w);
                float2 gd1a = h2unpack(d1v.z), gd1b = h2unpack(d1v.w);
                float u0 = fsilu(acc1[2*s][0]   + gs0a.x + gd0a.x);
                float u1 = fsilu(acc1[2*s][1]   + gs0a.y + gd0a.y);
                float u2 = fsilu(acc1[2*s+1][0] + gs0b.x + gd0b.x);
                float u3 = fsilu(acc1[2*s+1][1] + gs0b.y + gd0b.y);
                float w0 = fsilu(acc1[2*s][2]   + gs1a.x + gd1a.x);
                float w1 = fsilu(acc1[2*s][3]   + gs1a.y + gd1a.y);
                float w2 = fsilu(acc1[2*s+1][2] + gs1b.x + gd1b.x);
                float w3 = fsilu(acc1[2*s+1][3] + gs1b.y + gd1b.y);
                a2f[s][0] = h2pack(u0, u1);
                a2f[s][1] = h2pack(w0, w1);
                a2f[s][2] = h2pack(u2, u3);
                a2f[s][3] = h2pack(w2, w3);
            }
        }

        // ---- prefetch NEXT tile's gather rows + efeat rows into L2 ----
        if (hasnext) {
            asm volatile("prefetch.global.L2 [%0];" :: "l"(g_src_proj + (size_t)nsi0 * HID + qcol * 32));
            asm volatile("prefetch.global.L2 [%0];" :: "l"(g_dst_proj + (size_t)ndi0 * HID + qcol * 32));
            asm volatile("prefetch.global.L2 [%0];" :: "l"(g_src_proj + (size_t)nsi1 * HID + qcol * 32));
            asm volatile("prefetch.global.L2 [%0];" :: "l"(g_dst_proj + (size_t)ndi1 * HID + qcol * 32));
            asm volatile("prefetch.global.L2 [%0];" :: "l"(efeat + (size_t)nge0 * IN_DIM + qcol * 16));
            asm volatile("prefetch.global.L2 [%0];" :: "l"(efeat + (size_t)nge1 * IN_DIM + qcol * 16));
        }

        // ---- GEMM2 ----
        float acc2[16][4];
        #pragma unroll
        for (int j = 0; j < 16; j++) { acc2[j][0]=0.f; acc2[j][1]=0.f; acc2[j][2]=0.f; acc2[j][3]=0.f; }
        #pragma unroll
        for (int s2 = 0; s2 < 4; s2++) {
            #pragma unroll
            for (int jg = 0; jg < 4; jg++) {
                const int n0 = 4 * jg;
                uint4 b0 = f2[((n0 + 0) * 4 + s2) * 32 + lane];
                uint4 b1 = f2[((n0 + 1) * 4 + s2) * 32 + lane];
                uint4 b2 = f2[((n0 + 2) * 4 + s2) * 32 + lane];
                uint4 b3 = f2[((n0 + 3) * 4 + s2) * 32 + lane];
                mma_f16(acc2[n0+0], a2f[2*s2],   b0.x, b0.y);
                mma_f16(acc2[n0+1], a2f[2*s2],   b1.x, b1.y);
                mma_f16(acc2[n0+2], a2f[2*s2],   b2.x, b2.y);
                mma_f16(acc2[n0+3], a2f[2*s2],   b3.x, b3.y);
                mma_f16(acc2[n0+0], a2f[2*s2+1], b0.z, b0.w);
                mma_f16(acc2[n0+1], a2f[2*s2+1], b1.z, b1.w);
                mma_f16(acc2[n0+2], a2f[2*s2+1], b2.z, b2.w);
                mma_f16(acc2[n0+3], a2f[2*s2+1], b3.z, b3.w);
            }
        }

        // ---- bias + LayerNorm (quad shuffle) + store ----
        float s0 = 0.f, ss0 = 0.f, s1 = 0.f, ss1 = 0.f;
        #pragma unroll
        for (int j = 0; j < 16; j++) {
            float2 bo = *(const float2*)(sBO + 8 * j + 2 * qcol);
            acc2[j][0] += bo.x; acc2[j][1] += bo.y;
            acc2[j][2] += bo.x; acc2[j][3] += bo.y;
            s0  += acc2[j][0] + acc2[j][1];
            ss0 += acc2[j][0] * acc2[j][0] + acc2[j][1] * acc2[j][1];
            s1  += acc2[j][2] + acc2[j][3];
            ss1 += acc2[j][2] * acc2[j][2] + acc2[j][3] * acc2[j][3];
        }
        s0  += __shfl_xor_sync(0xffffffffu, s0, 1);  s0  += __shfl_xor_sync(0xffffffffu, s0, 2);
        ss0 += __shfl_xor_sync(0xffffffffu, ss0, 1); ss0 += __shfl_xor_sync(0xffffffffu, ss0, 2);
        s1  += __shfl_xor_sync(0xffffffffu, s1, 1);  s1  += __shfl_xor_sync(0xffffffffu, s1, 2);
        ss1 += __shfl_xor_sync(0xffffffffu, ss1, 1); ss1 += __shfl_xor_sync(0xffffffffu, ss1, 2);

        const float m0 = s0 * (1.0f / OUTD);
        const float v0 = ss0 * (1.0f / OUTD) - m0 * m0;
        const float i0 = rsqrtf(v0 + 1e-5f);
        const float m1 = s1 * (1.0f / OUTD);
        const float v1 = ss1 * (1.0f / OUTD) - m1 * m1;
        const float i1 = rsqrtf(v1 + 1e-5f);

        const bool st0 = (er0i < E), st1 = (er1i < E);
        float* o0 = out + (size_t)er0i * OUTD + 2 * qcol;
        float* o1 = out + (size_t)er1i * OUTD + 2 * qcol;
        #pragma unroll
        for (int j = 0; j < 16; j++) {
            float2 ga = *(const float2*)(sGA + 8 * j + 2 * qcol);
            float2 be = *(const float2*)(sBE + 8 * j + 2 * qcol);
            if (st0) {
                float2 w;
                w.x = (acc2[j][0] - m0) * i0 * ga.x + be.x;
                w.y = (acc2[j][1] - m0) * i0 * ga.y + be.y;
                *(float2*)(o0 + 8 * j) = w;
            }
            if (st1) {
                float2 w;
                w.x = (acc2[j][2] - m1) * i1 * ga.x + be.x;
                w.y = (acc2[j][3] - m1) * i1 * ga.y + be.y;
                *(float2*)(o1 + 8 * j) = w;
            }
        }

        tile = ntile;
        si0 = nsi0; di0 = ndi0; si1 = nsi1; di1 = ndi1;
    }
}

// ---------------------------------------------------------------------------
extern "C" void kernel_launch(void* const* d_in, const int* in_sizes, int n_in,
                              void* d_out, int out_size)
{
    const float* efeat    = (const float*)d_in[0];
    const float* src_feat = (const float*)d_in[1];
    const float* dst_feat = (const float*)d_in[2];
    const int*   src_idx  = (const int*)d_in[3];
    const int*   dst_idx  = (const int*)d_in[4];
    const float* W_efeat  = (const float*)d_in[5];
    const float* W_src    = (const float*)d_in[6];
    const float* W_dst    = (const float*)d_in[7];
    const float* b1       = (const float*)d_in[8];
    const float* W_out    = (const float*)d_in[9];
    const float* b_out    = (const float*)d_in[10];
    const float* ln_gamma = (const float*)d_in[11];
    const float* ln_beta  = (const float*)d_in[12];
    float* out = (float*)d_out;

    const int E  = in_sizes[0] / IN_DIM;
    const int Nn = in_sizes[1] / IN_DIM;
    const int ntiles  = (E + ETILE - 1) / ETILE;
    const int ntilesN = (Nn + NROWS_N - 1) / NROWS_N;

    cudaFuncSetAttribute(node_mma_kernel, cudaFuncAttributeMaxDynamicSharedMemorySize, SMEM_NODE_BYTES);
    cudaFuncSetAttribute(edge_f16_kernel, cudaFuncAttributeMaxDynamicSharedMemorySize, SMEM_EDGE_BYTES);

    int nsm = 148;
    cudaDeviceGetAttribute(&nsm, cudaDevAttrMultiProcessorCount, 0);

    int gridN = 2 * ntilesN < nsm ? 2 * ntilesN : nsm;
    node_mma_kernel<<<gridN, NTHR, SMEM_NODE_BYTES>>>(src_feat, dst_feat, W_src, W_dst, b1, Nn, ntilesN);

    int grid = (ntiles < nsm) ? ntiles : nsm;
    edge_f16_kernel<<<grid, NTHR, SMEM_EDGE_BYTES>>>(efeat, src_idx, dst_idx, W_efeat, W_out,
                                                     b_out, ln_gamma, ln_beta, out, E, ntiles);
}